// round 5
// baseline (speedup 1.0000x reference)
#include <cuda_runtime.h>
#include <cuda_bf16.h>
#include <cstddef>
#include <cstdint>

#define NN 100000
#define NE 1000000
#define DD 300
#define DV 75          // float4 per fp32 row
#define MP 100096      // NN padded to 128
#define KP1 320        // K=300 padded
#define NP  320        // N=300 padded

typedef __nv_bfloat16 bf16;
typedef __nv_bfloat162 bf162;

// ---------------- scratch (device globals; no allocation allowed) ----------
__device__ __align__(16) float g_deg[4 * NN];
__device__ __align__(16) float g_agg_r[(size_t)NN * DD];
__device__ __align__(16) float g_agg_c[(size_t)NN * DD];
__device__ __align__(16) float g_merged[(size_t)NN * 2 * DD];

// bf16 hi/lo operand planes (padded, M x K row-major)
__device__ __align__(16) bf16 g_aggr_h[(size_t)MP * KP1];
__device__ __align__(16) bf16 g_aggr_l[(size_t)MP * KP1];
__device__ __align__(16) bf16 g_aggc_h[(size_t)MP * KP1];
__device__ __align__(16) bf16 g_aggc_l[(size_t)MP * KP1];
__device__ __align__(16) bf16 g_rowg_h[(size_t)MP * KP1];
__device__ __align__(16) bf16 g_rowg_l[(size_t)MP * KP1];
__device__ __align__(16) bf16 g_colg_h[(size_t)MP * KP1];
__device__ __align__(16) bf16 g_colg_l[(size_t)MP * KP1];
// weight planes: K x N row-major (KP1 x NP)
__device__ __align__(16) bf16 g_Wr_h[KP1 * NP],  g_Wr_l[KP1 * NP];
__device__ __align__(16) bf16 g_Wc_h[KP1 * NP],  g_Wc_l[KP1 * NP];
__device__ __align__(16) bf16 g_Wrs_h[KP1 * NP], g_Wrs_l[KP1 * NP];
__device__ __align__(16) bf16 g_Wcs_h[KP1 * NP], g_Wcs_l[KP1 * NP];
__device__ __align__(16) bf16 g_Wmt_h[KP1 * NP], g_Wmt_l[KP1 * NP];
__device__ __align__(16) bf16 g_Wmb_h[KP1 * NP], g_Wmb_l[KP1 * NP];

// ---------------- helpers ----------------------------------------------------
__device__ __forceinline__ void split_bf16(float v, bf16& h, bf16& l) {
    h = __float2bfloat16(v);
    l = __float2bfloat16(v - __bfloat162float(h));
}
__device__ __forceinline__ void cp16(uint32_t dst, const void* src) {
    asm volatile("cp.async.cg.shared.global [%0], [%1], 16;" :: "r"(dst), "l"(src));
}
__device__ __forceinline__ void ldsm_x4(uint32_t& r0, uint32_t& r1, uint32_t& r2, uint32_t& r3,
                                        uint32_t addr) {
    asm volatile("ldmatrix.sync.aligned.m8n8.x4.shared.b16 {%0,%1,%2,%3}, [%4];"
                 : "=r"(r0), "=r"(r1), "=r"(r2), "=r"(r3) : "r"(addr));
}
__device__ __forceinline__ void ldsm_x4_t(uint32_t& r0, uint32_t& r1, uint32_t& r2, uint32_t& r3,
                                          uint32_t addr) {
    asm volatile("ldmatrix.sync.aligned.m8n8.x4.trans.shared.b16 {%0,%1,%2,%3}, [%4];"
                 : "=r"(r0), "=r"(r1), "=r"(r2), "=r"(r3) : "r"(addr));
}
__device__ __forceinline__ void mma_bf16(float* c, const uint32_t* a, const uint32_t* b) {
    asm volatile("mma.sync.aligned.m16n8k16.row.col.f32.bf16.bf16.f32 "
                 "{%0,%1,%2,%3}, {%4,%5,%6,%7}, {%8,%9}, {%0,%1,%2,%3};"
                 : "+f"(c[0]), "+f"(c[1]), "+f"(c[2]), "+f"(c[3])
                 : "r"(a[0]), "r"(a[1]), "r"(a[2]), "r"(a[3]), "r"(b[0]), "r"(b[1]));
}

// ---------------- zero ------------------------------------------------------
__global__ void zero_kernel(float4* __restrict__ p, long n4) {
    long i = (long)blockIdx.x * blockDim.x + threadIdx.x;
    long stride = (long)gridDim.x * blockDim.x;
    float4 z = make_float4(0.f, 0.f, 0.f, 0.f);
    for (; i < n4; i += stride) p[i] = z;
}

// ---------------- degrees ---------------------------------------------------
__global__ void degree_kernel(const int* __restrict__ er, const int* __restrict__ ec) {
    int i = blockIdx.x * blockDim.x + threadIdx.x;
    if (i < NE) {
        atomicAdd(&g_deg[0 * NN + er[i]],      1.f);
        atomicAdd(&g_deg[1 * NN + er[NE + i]], 1.f);
        atomicAdd(&g_deg[2 * NN + ec[i]],      1.f);
        atomicAdd(&g_deg[3 * NN + ec[NE + i]], 1.f);
    }
}

__global__ void norm_kernel() {
    int i = blockIdx.x * blockDim.x + threadIdx.x;
    if (i < 4 * NN) {
        float d = g_deg[i];
        g_deg[i] = (d > 0.f) ? rsqrtf(d) : 0.f;
    }
}

// ---------------- edge scatter ----------------------------------------------
__global__ void scatter_kernel(const int* __restrict__ src, const int* __restrict__ dst,
                               const float* __restrict__ nsrc,
                               const float4* __restrict__ x, float4* __restrict__ agg) {
    long i = (long)blockIdx.x * blockDim.x + threadIdx.x;
    if (i >= (long)NE * DV) return;
    int e = (int)(i / DV);
    int c = (int)(i - (long)e * DV);
    int s = src[e];
    int d = dst[e];
    float ns = nsrc[s];
    float4 v = x[(size_t)s * DV + c];
    float4* p = &agg[(size_t)d * DV + c];
    asm volatile("red.global.add.v4.f32 [%0], {%1, %2, %3, %4};"
                 :: "l"(p), "f"(v.x * ns), "f"(v.y * ns), "f"(v.z * ns), "f"(v.w * ns)
                 : "memory");
}

// ---------------- converts ---------------------------------------------------
__global__ void agg_convert_kernel(const float4* __restrict__ agg,
                                   const float* __restrict__ ndst,
                                   bf16* __restrict__ Ah, bf16* __restrict__ Al) {
    long idx = (long)blockIdx.x * blockDim.x + threadIdx.x;
    if (idx >= (long)MP * (KP1 / 4)) return;
    int row = (int)(idx / (KP1 / 4));
    int kq  = (int)(idx - (long)row * (KP1 / 4));
    float4 v = make_float4(0.f, 0.f, 0.f, 0.f);
    if (row < NN && kq < DV) {
        v = agg[(size_t)row * DV + kq];
        float s = ndst[row];
        v.x *= s; v.y *= s; v.z *= s; v.w *= s;
    }
    bf16 h0, h1, h2, h3, l0, l1, l2, l3;
    split_bf16(v.x, h0, l0); split_bf16(v.y, h1, l1);
    split_bf16(v.z, h2, l2); split_bf16(v.w, h3, l3);
    size_t off = (size_t)row * KP1 + kq * 4;
    *(bf162*)&Ah[off]     = bf162(h0, h1);
    *(bf162*)&Ah[off + 2] = bf162(h2, h3);
    *(bf162*)&Al[off]     = bf162(l0, l1);
    *(bf162*)&Al[off + 2] = bf162(l2, l3);
}

// weight (K x Ncols fp32 row-major) -> hi/lo planes (KP1 x NP), zero padded
__global__ void w_convert_kernel(const float* __restrict__ W, int K, int Ncols,
                                 bf16* __restrict__ Wh, bf16* __restrict__ Wl) {
    int idx = blockIdx.x * blockDim.x + threadIdx.x;
    if (idx >= KP1 * NP) return;
    int k = idx / NP;
    int n = idx - k * NP;
    float v = (k < K && n < Ncols) ? W[(size_t)k * Ncols + n] : 0.f;
    bf16 h, l;
    split_bf16(v, h, l);
    Wh[idx] = h; Wl[idx] = l;
}

// ================= A-panel-resident tensor-core GEMM =========================
// C(M x 320) = A(M x 320) @ W(320 x 320), 3-pass bf16 split, mma.sync.
// Per CTA: M=128 rows, ALL 320 cols; A panel resident in SMEM; B streamed from L2.
#define GBM 128
#define GBN 64
#define GK 64
#define NB 5
#define NKT 5
#define ASTR 328                          // 320 + 8 pad halves
#define A_PLANE (GBM * ASTR * 2)          // 83968 bytes
#define BSTR 72
#define B_PLANE (GK * BSTR * 2)           // 9216 bytes
#define B_STAGE (2 * B_PLANE)             // 18432
#define SMEM_GEMM (2 * A_PLANE + 2 * B_STAGE)  // 204800

__global__ __launch_bounds__(256) void gemm_ar_kernel(
    const bf16* __restrict__ Aph, const bf16* __restrict__ Apl,
    const bf16* __restrict__ Bph, const bf16* __restrict__ Bpl,
    const float* __restrict__ bias,
    int M, int Ncols, int mode, int relu, int accum,
    float* __restrict__ Cf, int ldc,
    bf16* __restrict__ Ch, bf16* __restrict__ Cl, int ldcp)
{
    extern __shared__ __align__(16) char smem[];
    const uint32_t sAh = (uint32_t)__cvta_generic_to_shared(smem);
    const uint32_t sAl = sAh + A_PLANE;
    const uint32_t sB0 = sAl + A_PLANE;

    const int t = threadIdx.x;
    const int wid = t >> 5;
    const int lane = t & 31;
    const int warp_m = wid >> 1;
    const int warp_n = wid & 1;
    const int m0 = blockIdx.x * GBM;

    // ---- A panel load: 128 rows x 40 16B-chunks per plane (5120 chunks) ----
    {
        #pragma unroll
        for (int i = 0; i < 20; i++) {
            int idx = i * 256 + t;
            int r = idx / 40;
            int c = idx - r * 40;
            uint32_t d = (uint32_t)(r * ASTR + c * 8) * 2;
            size_t s = (size_t)(m0 + r) * KP1 + c * 8;
            cp16(sAh + d, Aph + s);
            cp16(sAl + d, Apl + s);
        }
    }

    // B tile loader: 64 k-rows x 8 chunks per plane (512 chunks)
    auto load_B = [&](int stage, int nb, int kt) {
        const uint32_t bh = sB0 + (uint32_t)stage * B_STAGE;
        const uint32_t bl = bh + B_PLANE;
        #pragma unroll
        for (int i = 0; i < 2; i++) {
            int idx = i * 256 + t;
            int r = idx >> 3;
            int c = idx & 7;
            uint32_t d = (uint32_t)(r * BSTR + c * 8) * 2;
            size_t s = (size_t)(kt * GK + r) * NP + nb * GBN + c * 8;
            cp16(bh + d, Bph + s);
            cp16(bl + d, Bpl + s);
        }
        asm volatile("cp.async.commit_group;");
    };

    load_B(0, 0, 0);   // group 0 = A panel + B(0,0)

    float acc[2][4][4];
    #pragma unroll
    for (int mi = 0; mi < 2; mi++)
        #pragma unroll
        for (int ni = 0; ni < 4; ni++)
            #pragma unroll
            for (int j = 0; j < 4; j++) acc[mi][ni][j] = 0.f;

    const int lrow = lane & 15;
    const int lcol8 = (lane >> 4) << 3;
    const int g = lane >> 2;
    const int tig = lane & 3;

    for (int it = 0; it < NB * NKT; it++) {
        const int nb = it / NKT;
        const int kt = it - nb * NKT;
        if (it + 1 < NB * NKT) {
            const int it2 = it + 1;
            load_B(it2 & 1, it2 / NKT, it2 - (it2 / NKT) * NKT);
            asm volatile("cp.async.wait_group 1;");
        } else {
            asm volatile("cp.async.wait_group 0;");
        }
        __syncthreads();

        const uint32_t boff = sB0 + (uint32_t)(it & 1) * B_STAGE;

        #pragma unroll
        for (int ks = 0; ks < 4; ks++) {
            uint32_t ah[2][4], al[2][4];
            #pragma unroll
            for (int mi = 0; mi < 2; mi++) {
                int row = warp_m * 32 + mi * 16 + lrow;
                int col = kt * GK + ks * 16 + lcol8;
                uint32_t off = (uint32_t)(row * ASTR + col) * 2;
                ldsm_x4(ah[mi][0], ah[mi][1], ah[mi][2], ah[mi][3], sAh + off);
                ldsm_x4(al[mi][0], al[mi][1], al[mi][2], al[mi][3], sAl + off);
            }
            uint32_t bh[4][2], bl[4][2];
            #pragma unroll
            for (int nj = 0; nj < 2; nj++) {
                int row = ks * 16 + lrow;
                int col = warp_n * 32 + nj * 16 + lcol8;
                uint32_t off = (uint32_t)(row * BSTR + col) * 2;
                uint32_t r0, r1, r2, r3;
                ldsm_x4_t(r0, r1, r2, r3, boff + off);
                bh[nj * 2 + 0][0] = r0; bh[nj * 2 + 0][1] = r1;
                bh[nj * 2 + 1][0] = r2; bh[nj * 2 + 1][1] = r3;
                ldsm_x4_t(r0, r1, r2, r3, boff + B_PLANE + off);
                bl[nj * 2 + 0][0] = r0; bl[nj * 2 + 0][1] = r1;
                bl[nj * 2 + 1][0] = r2; bl[nj * 2 + 1][1] = r3;
            }
            #pragma unroll
            for (int mi = 0; mi < 2; mi++)
                #pragma unroll
                for (int ni = 0; ni < 4; ni++) {
                    mma_bf16(acc[mi][ni], ah[mi], bh[ni]);
                    mma_bf16(acc[mi][ni], ah[mi], bl[ni]);
                    mma_bf16(acc[mi][ni], al[mi], bh[ni]);
                }
        }

        // ---- epilogue for this column block ----
        if (kt == NKT - 1) {
            const int n0 = nb * GBN;
            #pragma unroll
            for (int mi = 0; mi < 2; mi++) {
                #pragma unroll
                for (int ni = 0; ni < 4; ni++) {
                    int col = n0 + warp_n * 32 + ni * 8 + tig * 2;
                    float bx = 0.f, by = 0.f;
                    if (bias != nullptr && col < Ncols) { bx = bias[col]; by = bias[col + 1]; }
                    #pragma unroll
                    for (int rr = 0; rr < 2; rr++) {
                        int row = m0 + warp_m * 32 + mi * 16 + g + rr * 8;
                        float vx = acc[mi][ni][rr * 2 + 0] + bx;
                        float vy = acc[mi][ni][rr * 2 + 1] + by;
                        if (relu) { vx = fmaxf(vx, 0.f); vy = fmaxf(vy, 0.f); }
                        if (mode == 0) {
                            if (row < M && col < Ncols) {
                                float* p = Cf + (size_t)row * ldc + col;
                                if (accum) {
                                    float2 old = *(float2*)p;
                                    vx += old.x; vy += old.y;
                                }
                                *(float2*)p = make_float2(vx, vy);
                            }
                        } else {
                            bool ok = (row < M) && (col < Ncols);
                            if (!ok) { vx = 0.f; vy = 0.f; }
                            bf16 hx, lx, hy, ly;
                            split_bf16(vx, hx, lx);
                            split_bf16(vy, hy, ly);
                            size_t o = (size_t)row * ldcp + col;
                            *(bf162*)&Ch[o] = bf162(hx, hy);
                            *(bf162*)&Cl[o] = bf162(lx, ly);
                        }
                        acc[mi][ni][rr * 2 + 0] = 0.f;
                        acc[mi][ni][rr * 2 + 1] = 0.f;
                    }
                }
            }
        }
        __syncthreads();
    }
}

// ---------------- LayerNorm (fp32, in place) --------------------------------
__global__ void ln_kernel(float* __restrict__ X, int ld,
                          const float* __restrict__ gamma,
                          const float* __restrict__ beta, int M) {
    int warp = (int)((blockIdx.x * (long)blockDim.x + threadIdx.x) >> 5);
    int lane = threadIdx.x & 31;
    if (warp >= M) return;
    float* p = X + (size_t)warp * ld;
    float v[10];
    float sum = 0.f;
    #pragma unroll
    for (int k = 0; k < 10; k++) {
        int c = lane + 32 * k;
        v[k] = (c < DD) ? p[c] : 0.f;
        sum += v[k];
    }
    #pragma unroll
    for (int o = 16; o > 0; o >>= 1) sum += __shfl_xor_sync(0xFFFFFFFFu, sum, o);
    float mu = sum * (1.f / DD);
    float var = 0.f;
    #pragma unroll
    for (int k = 0; k < 10; k++) {
        int c = lane + 32 * k;
        float d = (c < DD) ? (v[k] - mu) : 0.f;
        var += d * d;
    }
    #pragma unroll
    for (int o = 16; o > 0; o >>= 1) var += __shfl_xor_sync(0xFFFFFFFFu, var, o);
    float rsig = rsqrtf(var * (1.f / DD) + 1e-5f);
    #pragma unroll
    for (int k = 0; k < 10; k++) {
        int c = lane + 32 * k;
        if (c < DD) p[c] = (v[k] - mu) * rsig * gamma[c] + beta[c];
    }
}

// LN both halves of merged row -> two bf16 hi/lo plane pairs (MP x KP1).
// Tail rows [NN,MP) of the target planes are already zero (agg_convert wrote them).
__global__ void ln_merged_kernel(const float* __restrict__ merged,
                                 const float* __restrict__ g0, const float* __restrict__ b0,
                                 const float* __restrict__ g1, const float* __restrict__ b1,
                                 bf16* __restrict__ R_h, bf16* __restrict__ R_l,
                                 bf16* __restrict__ C_h, bf16* __restrict__ C_l) {
    int warp = (int)((blockIdx.x * (long)blockDim.x + threadIdx.x) >> 5);
    int lane = threadIdx.x & 31;
    if (warp >= NN) return;
    const float* prow = merged + (size_t)warp * (2 * DD);
    size_t orow = (size_t)warp * KP1;
    #pragma unroll
    for (int half = 0; half < 2; half++) {
        const float* p = prow + half * DD;
        const float* gamma = half ? g1 : g0;
        const float* beta  = half ? b1 : b0;
        bf16* Dh = half ? C_h : R_h;
        bf16* Dl = half ? C_l : R_l;
        float v[10];
        float sum = 0.f;
        #pragma unroll
        for (int k = 0; k < 10; k++) {
            int c = lane + 32 * k;
            v[k] = (c < DD) ? p[c] : 0.f;
            sum += v[k];
        }
        #pragma unroll
        for (int o = 16; o > 0; o >>= 1) sum += __shfl_xor_sync(0xFFFFFFFFu, sum, o);
        float mu = sum * (1.f / DD);
        float var = 0.f;
        #pragma unroll
        for (int k = 0; k < 10; k++) {
            int c = lane + 32 * k;
            float d = (c < DD) ? (v[k] - mu) : 0.f;
            var += d * d;
        }
        #pragma unroll
        for (int o = 16; o > 0; o >>= 1) var += __shfl_xor_sync(0xFFFFFFFFu, var, o);
        float rsig = rsqrtf(var * (1.f / DD) + 1e-5f);
        #pragma unroll
        for (int k = 0; k < 10; k++) {
            int c = lane + 32 * k;
            if (c < DD) {
                float w = (v[k] - mu) * rsig * gamma[c] + beta[c];
                bf16 h, l;
                split_bf16(w, h, l);
                Dh[orow + c] = h;
                Dl[orow + c] = l;
            }
        }
        // zero pad cols [300, 320)
        if (lane < 20) {
            bf16 z = __float2bfloat16(0.f);
            Dh[orow + 300 + lane] = z;
            Dl[orow + 300 + lane] = z;
        }
    }
}

// ---------------- launch ----------------------------------------------------
extern "C" void kernel_launch(void* const* d_in, const int* in_sizes, int n_in,
                              void* d_out, int out_size) {
    const float* x    = (const float*)d_in[0];
    const int*   er   = (const int*)d_in[1];
    const int*   ec   = (const int*)d_in[2];
    const float* Wr   = (const float*)d_in[3];
    const float* br   = (const float*)d_in[4];
    const float* Wc   = (const float*)d_in[5];
    const float* bc   = (const float*)d_in[6];
    const float* Wrs  = (const float*)d_in[7];
    const float* brs  = (const float*)d_in[8];
    const float* g_rs = (const float*)d_in[9];
    const float* b_rs = (const float*)d_in[10];
    const float* Wcs  = (const float*)d_in[11];
    const float* bcs  = (const float*)d_in[12];
    const float* g_cs = (const float*)d_in[13];
    const float* b_cs = (const float*)d_in[14];
    const float* Wm   = (const float*)d_in[15];
    const float* bm   = (const float*)d_in[16];
    const float* g_m  = (const float*)d_in[17];
    const float* b_m  = (const float*)d_in[18];
    float* out = (float*)d_out;

    float *deg, *aggr, *aggc, *merged;
    cudaGetSymbolAddress((void**)&deg,    g_deg);
    cudaGetSymbolAddress((void**)&aggr,   g_agg_r);
    cudaGetSymbolAddress((void**)&aggc,   g_agg_c);
    cudaGetSymbolAddress((void**)&merged, g_merged);

    bf16 *aggr_h, *aggr_l, *aggc_h, *aggc_l, *rowg_h, *rowg_l, *colg_h, *colg_l;
    bf16 *Wr_h, *Wr_l, *Wc_h, *Wc_l, *Wrs_h, *Wrs_l, *Wcs_h, *Wcs_l;
    bf16 *Wmt_h, *Wmt_l, *Wmb_h, *Wmb_l;
    cudaGetSymbolAddress((void**)&aggr_h, g_aggr_h);
    cudaGetSymbolAddress((void**)&aggr_l, g_aggr_l);
    cudaGetSymbolAddress((void**)&aggc_h, g_aggc_h);
    cudaGetSymbolAddress((void**)&aggc_l, g_aggc_l);
    cudaGetSymbolAddress((void**)&rowg_h, g_rowg_h);
    cudaGetSymbolAddress((void**)&rowg_l, g_rowg_l);
    cudaGetSymbolAddress((void**)&colg_h, g_colg_h);
    cudaGetSymbolAddress((void**)&colg_l, g_colg_l);
    cudaGetSymbolAddress((void**)&Wr_h,  g_Wr_h);   cudaGetSymbolAddress((void**)&Wr_l,  g_Wr_l);
    cudaGetSymbolAddress((void**)&Wc_h,  g_Wc_h);   cudaGetSymbolAddress((void**)&Wc_l,  g_Wc_l);
    cudaGetSymbolAddress((void**)&Wrs_h, g_Wrs_h);  cudaGetSymbolAddress((void**)&Wrs_l, g_Wrs_l);
    cudaGetSymbolAddress((void**)&Wcs_h, g_Wcs_h);  cudaGetSymbolAddress((void**)&Wcs_l, g_Wcs_l);
    cudaGetSymbolAddress((void**)&Wmt_h, g_Wmt_h);  cudaGetSymbolAddress((void**)&Wmt_l, g_Wmt_l);
    cudaGetSymbolAddress((void**)&Wmb_h, g_Wmb_h);  cudaGetSymbolAddress((void**)&Wmb_l, g_Wmb_l);

    cudaFuncSetAttribute(gemm_ar_kernel,
                         cudaFuncAttributeMaxDynamicSharedMemorySize, SMEM_GEMM);

    // zero degree + aggregation buffers
    zero_kernel<<<1024, 256>>>((float4*)deg, (long)(4 * NN) / 4);
    zero_kernel<<<29297, 256>>>((float4*)aggr, (long)NN * DV);
    zero_kernel<<<29297, 256>>>((float4*)aggc, (long)NN * DV);

    // weight splits (K x N planes); merge weight split into top/bottom K-halves
    int wgrid = (KP1 * NP + 255) / 256;
    w_convert_kernel<<<wgrid, 256>>>(Wr,  DD, DD, Wr_h,  Wr_l);
    w_convert_kernel<<<wgrid, 256>>>(Wc,  DD, DD, Wc_h,  Wc_l);
    w_convert_kernel<<<wgrid, 256>>>(Wrs, DD, DD, Wrs_h, Wrs_l);
    w_convert_kernel<<<wgrid, 256>>>(Wcs, DD, DD, Wcs_h, Wcs_l);
    w_convert_kernel<<<wgrid, 256>>>(Wm,            DD, DD, Wmt_h, Wmt_l);
    w_convert_kernel<<<wgrid, 256>>>(Wm + DD * DD,  DD, DD, Wmb_h, Wmb_l);

    // degrees -> rsqrt norms
    degree_kernel<<<(NE + 255) / 256, 256>>>(er, ec);
    norm_kernel<<<(4 * NN + 255) / 256, 256>>>();

    // edge scatter
    long sw = (long)NE * DV;
    int sgrid = (int)((sw + 255) / 256);
    scatter_kernel<<<sgrid, 256>>>(er, er + NE, deg + 0 * NN, (const float4*)x, (float4*)aggr);
    scatter_kernel<<<sgrid, 256>>>(ec, ec + NE, deg + 2 * NN, (const float4*)x, (float4*)aggc);

    // agg -> bf16 planes (applies dst norm; zero-pads cols and tail rows)
    long aw = (long)MP * (KP1 / 4);
    int agrid = (int)((aw + 255) / 256);
    agg_convert_kernel<<<agrid, 256>>>((const float4*)aggr, deg + 1 * NN, aggr_h, aggr_l);
    agg_convert_kernel<<<agrid, 256>>>((const float4*)aggc, deg + 3 * NN, aggc_h, aggc_l);

    const int GGRID = MP / GBM;   // 782

    // GraphConv GEMMs -> relu -> bf16 planes
    gemm_ar_kernel<<<GGRID, 256, SMEM_GEMM>>>(aggr_h, aggr_l, Wr_h, Wr_l, br,
        NN, DD, 1, 1, 0, nullptr, 0, rowg_h, rowg_l, KP1);
    gemm_ar_kernel<<<GGRID, 256, SMEM_GEMM>>>(aggc_h, aggc_l, Wc_h, Wc_l, bc,
        NN, DD, 1, 1, 0, nullptr, 0, colg_h, colg_l, KP1);

    // support GEMMs -> fp32 merged halves
    gemm_ar_kernel<<<GGRID, 256, SMEM_GEMM>>>(rowg_h, rowg_l, Wrs_h, Wrs_l, brs,
        NN, DD, 0, 0, 0, merged, 2 * DD, nullptr, nullptr, 0);
    gemm_ar_kernel<<<GGRID, 256, SMEM_GEMM>>>(colg_h, colg_l, Wcs_h, Wcs_l, bcs,
        NN, DD, 0, 0, 0, merged + DD, 2 * DD, nullptr, nullptr, 0);

    // LN both halves -> row/col LN planes (reuse agg plane buffers)
    int lngrid = (NN + 7) / 8;
    ln_merged_kernel<<<lngrid, 256>>>(merged, g_rs, b_rs, g_cs, b_cs,
                                      aggr_h, aggr_l, aggc_h, aggc_l);

    // merge GEMM as two K=320 passes: out = rowLN@WmTop + bm, then += colLN@WmBot
    gemm_ar_kernel<<<GGRID, 256, SMEM_GEMM>>>(aggr_h, aggr_l, Wmt_h, Wmt_l, bm,
        NN, DD, 0, 0, 0, out, DD, nullptr, nullptr, 0);
    gemm_ar_kernel<<<GGRID, 256, SMEM_GEMM>>>(aggc_h, aggc_l, Wmb_h, Wmb_l, nullptr,
        NN, DD, 0, 0, 1, out, DD, nullptr, nullptr, 0);

    // final LN
    ln_kernel<<<lngrid, 256>>>(out, DD, g_m, b_m, NN);
}

// round 6
// speedup vs baseline: 1.3423x; 1.3423x over previous
#include <cuda_runtime.h>
#include <cuda_bf16.h>
#include <cstddef>
#include <cstdint>

#define NN 100000
#define NE 1000000
#define DD 300
#define MP 100096      // NN padded to 128
#define KP1 320        // K=300 padded
#define NP  320        // N=300 padded

typedef __nv_bfloat16 bf16;
typedef __nv_bfloat162 bf162;

// ---------------- scratch (device globals; no allocation allowed) ----------
__device__ int   g_ideg[4 * NN];              // int degrees [out_r|in_r|out_c|in_c]
__device__ float g_deg[4 * NN];               // rsqrt norms, same layout
__device__ int   g_off_r[NN + 1], g_off_c[NN + 1];
__device__ int   g_cur_r[NN],     g_cur_c[NN];
__device__ int   g_csr_r[NE],     g_csr_c[NE];
__device__ __align__(16) float g_merged[(size_t)NN * 2 * DD];

// bf16 hi/lo operand planes (padded, M x K row-major)
__device__ __align__(16) bf16 g_aggr_h[(size_t)MP * KP1];
__device__ __align__(16) bf16 g_aggr_l[(size_t)MP * KP1];
__device__ __align__(16) bf16 g_aggc_h[(size_t)MP * KP1];
__device__ __align__(16) bf16 g_aggc_l[(size_t)MP * KP1];
__device__ __align__(16) bf16 g_rowg_h[(size_t)MP * KP1];
__device__ __align__(16) bf16 g_rowg_l[(size_t)MP * KP1];
__device__ __align__(16) bf16 g_colg_h[(size_t)MP * KP1];
__device__ __align__(16) bf16 g_colg_l[(size_t)MP * KP1];
// weight planes: K x N row-major (KP1 x NP)
__device__ __align__(16) bf16 g_Wr_h[KP1 * NP],  g_Wr_l[KP1 * NP];
__device__ __align__(16) bf16 g_Wc_h[KP1 * NP],  g_Wc_l[KP1 * NP];
__device__ __align__(16) bf16 g_Wrs_h[KP1 * NP], g_Wrs_l[KP1 * NP];
__device__ __align__(16) bf16 g_Wcs_h[KP1 * NP], g_Wcs_l[KP1 * NP];
__device__ __align__(16) bf16 g_Wmt_h[KP1 * NP], g_Wmt_l[KP1 * NP];
__device__ __align__(16) bf16 g_Wmb_h[KP1 * NP], g_Wmb_l[KP1 * NP];

// ---------------- helpers ----------------------------------------------------
__device__ __forceinline__ void split_bf16(float v, bf16& h, bf16& l) {
    h = __float2bfloat16(v);
    l = __float2bfloat16(v - __bfloat162float(h));
}
__device__ __forceinline__ void cp16(uint32_t dst, const void* src) {
    asm volatile("cp.async.cg.shared.global [%0], [%1], 16;" :: "r"(dst), "l"(src));
}
__device__ __forceinline__ void ldsm_x4(uint32_t& r0, uint32_t& r1, uint32_t& r2, uint32_t& r3,
                                        uint32_t addr) {
    asm volatile("ldmatrix.sync.aligned.m8n8.x4.shared.b16 {%0,%1,%2,%3}, [%4];"
                 : "=r"(r0), "=r"(r1), "=r"(r2), "=r"(r3) : "r"(addr));
}
__device__ __forceinline__ void ldsm_x4_t(uint32_t& r0, uint32_t& r1, uint32_t& r2, uint32_t& r3,
                                          uint32_t addr) {
    asm volatile("ldmatrix.sync.aligned.m8n8.x4.trans.shared.b16 {%0,%1,%2,%3}, [%4];"
                 : "=r"(r0), "=r"(r1), "=r"(r2), "=r"(r3) : "r"(addr));
}
__device__ __forceinline__ void mma_bf16(float* c, const uint32_t* a, const uint32_t* b) {
    asm volatile("mma.sync.aligned.m16n8k16.row.col.f32.bf16.bf16.f32 "
                 "{%0,%1,%2,%3}, {%4,%5,%6,%7}, {%8,%9}, {%0,%1,%2,%3};"
                 : "+f"(c[0]), "+f"(c[1]), "+f"(c[2]), "+f"(c[3])
                 : "r"(a[0]), "r"(a[1]), "r"(a[2]), "r"(a[3]), "r"(b[0]), "r"(b[1]));
}

// ---------------- graph preprocessing ----------------------------------------
__global__ void zero_ideg_kernel() {
    int i = blockIdx.x * blockDim.x + threadIdx.x;
    if (i < 4 * NN) g_ideg[i] = 0;
}

__global__ void degree_kernel(const int* __restrict__ er, const int* __restrict__ ec) {
    int i = blockIdx.x * blockDim.x + threadIdx.x;
    if (i < NE) {
        atomicAdd(&g_ideg[0 * NN + er[i]],      1);
        atomicAdd(&g_ideg[1 * NN + er[NE + i]], 1);
        atomicAdd(&g_ideg[2 * NN + ec[i]],      1);
        atomicAdd(&g_ideg[3 * NN + ec[NE + i]], 1);
    }
}

__global__ void norm_kernel() {
    int i = blockIdx.x * blockDim.x + threadIdx.x;
    if (i < 4 * NN) {
        int d = g_ideg[i];
        g_deg[i] = (d > 0) ? rsqrtf((float)d) : 0.f;
    }
}

// single-block exclusive scan of NN in-degrees -> offsets (+cursor copy)
#define SCAN_T 1024
#define SCAN_CH ((NN + SCAN_T - 1) / SCAN_T)   // 98
__global__ __launch_bounds__(SCAN_T) void scan_kernel(const int* __restrict__ deg,
                                                      int* __restrict__ off,
                                                      int* __restrict__ cur) {
    __shared__ int ss[SCAN_T];
    int t = threadIdx.x;
    int lo = t * SCAN_CH;
    int hi = lo + SCAN_CH; if (hi > NN) hi = NN;
    int s = 0;
    for (int i = lo; i < hi; i++) s += deg[i];
    ss[t] = s;
    __syncthreads();
    for (int d = 1; d < SCAN_T; d <<= 1) {
        int v = (t >= d) ? ss[t - d] : 0;
        __syncthreads();
        ss[t] += v;
        __syncthreads();
    }
    int run = ss[t] - s;   // exclusive prefix
    for (int i = lo; i < hi; i++) {
        off[i] = run; cur[i] = run; run += deg[i];
    }
    if (t == SCAN_T - 1) off[NN] = run;
}

__global__ void fill_kernel(const int* __restrict__ edges,
                            int* __restrict__ cur, int* __restrict__ csr) {
    int i = blockIdx.x * blockDim.x + threadIdx.x;
    if (i < NE) {
        int s = edges[i];
        int d = edges[NE + i];
        int pos = atomicAdd(&cur[d], 1);
        csr[pos] = s;
    }
}

// one warp per node: acc = sum_in x[src]*nsrc[src]; out = split(acc*ndst) -> planes
__global__ __launch_bounds__(256) void gather_kernel(
    const int* __restrict__ csr, const int* __restrict__ off,
    const float* __restrict__ nsrc, const float* __restrict__ ndst,
    const float* __restrict__ x,
    bf16* __restrict__ Ah, bf16* __restrict__ Al) {
    int warp = (int)((blockIdx.x * (long)blockDim.x + threadIdx.x) >> 5);
    int lane = threadIdx.x & 31;
    if (warp >= NN) return;
    int o0 = off[warp], o1 = off[warp + 1];
    float acc[10];
    #pragma unroll
    for (int k = 0; k < 10; k++) acc[k] = 0.f;
    for (int j = o0; j < o1; j++) {
        int s = csr[j];
        float ns = nsrc[s];
        const float* xr = x + (size_t)s * DD;
        #pragma unroll
        for (int k = 0; k < 9; k++) acc[k] += xr[lane + 32 * k] * ns;
        if (lane < 12) acc[9] += xr[lane + 288] * ns;
    }
    float nd = ndst[warp];
    size_t orow = (size_t)warp * KP1;
    #pragma unroll
    for (int k = 0; k < 10; k++) {
        int c = lane + 32 * k;
        if (c < DD) {
            bf16 h, l;
            split_bf16(acc[k] * nd, h, l);
            Ah[orow + c] = h;
            Al[orow + c] = l;
        }
    }
    if (lane < 20) {
        bf16 z = __float2bfloat16(0.f);
        Ah[orow + 300 + lane] = z;
        Al[orow + 300 + lane] = z;
    }
}

// zero tail rows [NN, MP) of the agg planes
__global__ void tail_zero_kernel() {
    int i = blockIdx.x * blockDim.x + threadIdx.x;
    const int n = (MP - NN) * KP1;    // 30720
    if (i < n) {
        size_t o = (size_t)NN * KP1 + i;
        bf16 z = __float2bfloat16(0.f);
        g_aggr_h[o] = z; g_aggr_l[o] = z;
        g_aggc_h[o] = z; g_aggc_l[o] = z;
    }
}

// weight (K x Ncols fp32 row-major) -> hi/lo planes (KP1 x NP), zero padded
__global__ void w_convert_kernel(const float* __restrict__ W, int K, int Ncols,
                                 bf16* __restrict__ Wh, bf16* __restrict__ Wl) {
    int idx = blockIdx.x * blockDim.x + threadIdx.x;
    if (idx >= KP1 * NP) return;
    int k = idx / NP;
    int n = idx - k * NP;
    float v = (k < K && n < Ncols) ? W[(size_t)k * Ncols + n] : 0.f;
    bf16 h, l;
    split_bf16(v, h, l);
    Wh[idx] = h; Wl[idx] = l;
}

// ================= Tensor-core GEMM (R3 structure, + accum) =================
#define GBM 128
#define GBN 64
#define GBK 32
#define ASTR 40            // halves per A smem row (32 + 8 pad)
#define BSTR 72            // halves per B smem row (64 + 8 pad)
#define A_STAGE_B (GBM * ASTR * 2)   // 10240 bytes
#define B_STAGE_B (GBK * BSTR * 2)   // 4608 bytes
#define SMEM_GEMM (2 * (2 * A_STAGE_B + 2 * B_STAGE_B))  // 59392

__global__ __launch_bounds__(256) void gemm_tc2_kernel(
    const bf16* __restrict__ Aph, const bf16* __restrict__ Apl, int lda,
    const bf16* __restrict__ Bph, const bf16* __restrict__ Bpl,
    const float* __restrict__ bias,
    int M, int Ncols, int nK, int mode, int relu, int accum,
    float* __restrict__ Cf, int ldc,
    bf16* __restrict__ Ch, bf16* __restrict__ Cl, int ldcp)
{
    extern __shared__ __align__(16) char smem[];
    const uint32_t sAh = (uint32_t)__cvta_generic_to_shared(smem);
    const uint32_t sAl = sAh + 2 * A_STAGE_B;
    const uint32_t sBh = sAl + 2 * A_STAGE_B;
    const uint32_t sBl = sBh + 2 * B_STAGE_B;

    const int t = threadIdx.x;
    const int wid = t >> 5;
    const int lane = t & 31;
    const int warp_m = wid >> 1;
    const int warp_n = wid & 1;
    const int m0 = blockIdx.y * GBM;
    const int n0 = blockIdx.x * GBN;

    float acc[2][4][4];
    #pragma unroll
    for (int mi = 0; mi < 2; mi++)
        #pragma unroll
        for (int ni = 0; ni < 4; ni++)
            #pragma unroll
            for (int j = 0; j < 4; j++) acc[mi][ni][j] = 0.f;

    const int ar = t >> 2;
    const int ac = t & 3;
    const int br = t >> 3;
    const int bc = t & 7;

    auto load_stage = [&](int stage, int k0) {
        uint32_t asoff = (uint32_t)stage * A_STAGE_B;
        uint32_t bsoff = (uint32_t)stage * B_STAGE_B;
        #pragma unroll
        for (int i = 0; i < 2; i++) {
            int r = ar + i * 64;
            uint32_t d = asoff + (uint32_t)(r * ASTR + ac * 8) * 2;
            size_t s = (size_t)(m0 + r) * lda + k0 + ac * 8;
            cp16(sAh + d, Aph + s);
            cp16(sAl + d, Apl + s);
        }
        {
            uint32_t d = bsoff + (uint32_t)(br * BSTR + bc * 8) * 2;
            size_t s = (size_t)(k0 + br) * NP + n0 + bc * 8;
            cp16(sBh + d, Bph + s);
            cp16(sBl + d, Bpl + s);
        }
        asm volatile("cp.async.commit_group;");
    };

    load_stage(0, 0);

    const int lrow = lane & 15;
    const int lcol8 = (lane >> 4) << 3;

    for (int kt = 0; kt < nK; kt++) {
        if (kt + 1 < nK) {
            load_stage((kt + 1) & 1, (kt + 1) * GBK);
            asm volatile("cp.async.wait_group 1;");
        } else {
            asm volatile("cp.async.wait_group 0;");
        }
        __syncthreads();

        const int stage = kt & 1;
        const uint32_t aoff = (uint32_t)stage * A_STAGE_B;
        const uint32_t boff = (uint32_t)stage * B_STAGE_B;

        #pragma unroll
        for (int ks = 0; ks < 2; ks++) {
            uint32_t ah[2][4], al[2][4];
            #pragma unroll
            for (int mi = 0; mi < 2; mi++) {
                int row = warp_m * 32 + mi * 16 + lrow;
                int col = ks * 16 + lcol8;
                uint32_t off = aoff + (uint32_t)(row * ASTR + col) * 2;
                ldsm_x4(ah[mi][0], ah[mi][1], ah[mi][2], ah[mi][3], sAh + off);
                ldsm_x4(al[mi][0], al[mi][1], al[mi][2], al[mi][3], sAl + off);
            }
            uint32_t bh[4][2], bl[4][2];
            #pragma unroll
            for (int nj = 0; nj < 2; nj++) {
                int row = ks * 16 + lrow;
                int col = warp_n * 32 + nj * 16 + lcol8;
                uint32_t off = boff + (uint32_t)(row * BSTR + col) * 2;
                uint32_t r0, r1, r2, r3;
                ldsm_x4_t(r0, r1, r2, r3, sBh + off);
                bh[nj * 2 + 0][0] = r0; bh[nj * 2 + 0][1] = r1;
                bh[nj * 2 + 1][0] = r2; bh[nj * 2 + 1][1] = r3;
                ldsm_x4_t(r0, r1, r2, r3, sBl + off);
                bl[nj * 2 + 0][0] = r0; bl[nj * 2 + 0][1] = r1;
                bl[nj * 2 + 1][0] = r2; bl[nj * 2 + 1][1] = r3;
            }
            #pragma unroll
            for (int mi = 0; mi < 2; mi++)
                #pragma unroll
                for (int ni = 0; ni < 4; ni++) {
                    mma_bf16(acc[mi][ni], ah[mi], bh[ni]);
                    mma_bf16(acc[mi][ni], ah[mi], bl[ni]);
                    mma_bf16(acc[mi][ni], al[mi], bh[ni]);
                }
        }
        __syncthreads();
    }

    // ---- epilogue ----
    const int g = lane >> 2;
    const int tig = lane & 3;
    #pragma unroll
    for (int mi = 0; mi < 2; mi++) {
        #pragma unroll
        for (int ni = 0; ni < 4; ni++) {
            int col = n0 + warp_n * 32 + ni * 8 + tig * 2;
            float bx = 0.f, by = 0.f;
            if (bias != nullptr && col < Ncols) {
                bx = bias[col];
                if (col + 1 < Ncols) by = bias[col + 1];
            }
            #pragma unroll
            for (int rr = 0; rr < 2; rr++) {
                int row = m0 + warp_m * 32 + mi * 16 + g + rr * 8;
                float vx = acc[mi][ni][rr * 2 + 0] + bx;
                float vy = acc[mi][ni][rr * 2 + 1] + by;
                if (relu) { vx = fmaxf(vx, 0.f); vy = fmaxf(vy, 0.f); }
                if (mode == 0) {
                    if (row < M && col < Ncols) {
                        float* p = Cf + (size_t)row * ldc + col;
                        if (accum) {
                            float2 old = *(float2*)p;
                            vx += old.x; vy += old.y;
                        }
                        *(float2*)p = make_float2(vx, vy);
                    }
                } else {
                    bool ok = (row < M) && (col < Ncols);
                    if (!ok) { vx = 0.f; vy = 0.f; }
                    bf16 hx, lx, hy, ly;
                    split_bf16(vx, hx, lx);
                    split_bf16(vy, hy, ly);
                    size_t o = (size_t)row * ldcp + col;
                    *(bf162*)&Ch[o] = bf162(hx, hy);
                    *(bf162*)&Cl[o] = bf162(lx, ly);
                }
            }
        }
    }
}

// ---------------- LayerNorm (fp32, in place) --------------------------------
__global__ void ln_kernel(float* __restrict__ X, int ld,
                          const float* __restrict__ gamma,
                          const float* __restrict__ beta, int M) {
    int warp = (int)((blockIdx.x * (long)blockDim.x + threadIdx.x) >> 5);
    int lane = threadIdx.x & 31;
    if (warp >= M) return;
    float* p = X + (size_t)warp * ld;
    float v[10];
    float sum = 0.f;
    #pragma unroll
    for (int k = 0; k < 10; k++) {
        int c = lane + 32 * k;
        v[k] = (c < DD) ? p[c] : 0.f;
        sum += v[k];
    }
    #pragma unroll
    for (int o = 16; o > 0; o >>= 1) sum += __shfl_xor_sync(0xFFFFFFFFu, sum, o);
    float mu = sum * (1.f / DD);
    float var = 0.f;
    #pragma unroll
    for (int k = 0; k < 10; k++) {
        int c = lane + 32 * k;
        float d = (c < DD) ? (v[k] - mu) : 0.f;
        var += d * d;
    }
    #pragma unroll
    for (int o = 16; o > 0; o >>= 1) var += __shfl_xor_sync(0xFFFFFFFFu, var, o);
    float rsig = rsqrtf(var * (1.f / DD) + 1e-5f);
    #pragma unroll
    for (int k = 0; k < 10; k++) {
        int c = lane + 32 * k;
        if (c < DD) p[c] = (v[k] - mu) * rsig * gamma[c] + beta[c];
    }
}

// LN both halves of merged row -> two bf16 hi/lo plane pairs (MP x KP1)
__global__ void ln_merged_kernel(const float* __restrict__ merged,
                                 const float* __restrict__ g0, const float* __restrict__ b0,
                                 const float* __restrict__ g1, const float* __restrict__ b1,
                                 bf16* __restrict__ R_h, bf16* __restrict__ R_l,
                                 bf16* __restrict__ C_h, bf16* __restrict__ C_l) {
    int warp = (int)((blockIdx.x * (long)blockDim.x + threadIdx.x) >> 5);
    int lane = threadIdx.x & 31;
    if (warp >= NN) return;
    const float* prow = merged + (size_t)warp * (2 * DD);
    size_t orow = (size_t)warp * KP1;
    #pragma unroll
    for (int half = 0; half < 2; half++) {
        const float* p = prow + half * DD;
        const float* gamma = half ? g1 : g0;
        const float* beta  = half ? b1 : b0;
        bf16* Dh = half ? C_h : R_h;
        bf16* Dl = half ? C_l : R_l;
        float v[10];
        float sum = 0.f;
        #pragma unroll
        for (int k = 0; k < 10; k++) {
            int c = lane + 32 * k;
            v[k] = (c < DD) ? p[c] : 0.f;
            sum += v[k];
        }
        #pragma unroll
        for (int o = 16; o > 0; o >>= 1) sum += __shfl_xor_sync(0xFFFFFFFFu, sum, o);
        float mu = sum * (1.f / DD);
        float var = 0.f;
        #pragma unroll
        for (int k = 0; k < 10; k++) {
            int c = lane + 32 * k;
            float d = (c < DD) ? (v[k] - mu) : 0.f;
            var += d * d;
        }
        #pragma unroll
        for (int o = 16; o > 0; o >>= 1) var += __shfl_xor_sync(0xFFFFFFFFu, var, o);
        float rsig = rsqrtf(var * (1.f / DD) + 1e-5f);
        #pragma unroll
        for (int k = 0; k < 10; k++) {
            int c = lane + 32 * k;
            if (c < DD) {
                float w = (v[k] - mu) * rsig * gamma[c] + beta[c];
                bf16 h, l;
                split_bf16(w, h, l);
                Dh[orow + c] = h;
                Dl[orow + c] = l;
            }
        }
        if (lane < 20) {
            bf16 z = __float2bfloat16(0.f);
            Dh[orow + 300 + lane] = z;
            Dl[orow + 300 + lane] = z;
        }
    }
}

// ---------------- launch ----------------------------------------------------
extern "C" void kernel_launch(void* const* d_in, const int* in_sizes, int n_in,
                              void* d_out, int out_size) {
    const float* x    = (const float*)d_in[0];
    const int*   er   = (const int*)d_in[1];
    const int*   ec   = (const int*)d_in[2];
    const float* Wr   = (const float*)d_in[3];
    const float* br   = (const float*)d_in[4];
    const float* Wc   = (const float*)d_in[5];
    const float* bc   = (const float*)d_in[6];
    const float* Wrs  = (const float*)d_in[7];
    const float* brs  = (const float*)d_in[8];
    const float* g_rs = (const float*)d_in[9];
    const float* b_rs = (const float*)d_in[10];
    const float* Wcs  = (const float*)d_in[11];
    const float* bcs  = (const float*)d_in[12];
    const float* g_cs = (const float*)d_in[13];
    const float* b_cs = (const float*)d_in[14];
    const float* Wm   = (const float*)d_in[15];
    const float* bm   = (const float*)d_in[16];
    const float* g_m  = (const float*)d_in[17];
    const float* b_m  = (const float*)d_in[18];
    float* out = (float*)d_out;

    float *deg, *merged;
    cudaGetSymbolAddress((void**)&deg,    g_deg);
    cudaGetSymbolAddress((void**)&merged, g_merged);
    int *ideg, *off_r, *off_c, *cur_r, *cur_c, *csr_r, *csr_c;
    cudaGetSymbolAddress((void**)&ideg,  g_ideg);
    cudaGetSymbolAddress((void**)&off_r, g_off_r);
    cudaGetSymbolAddress((void**)&off_c, g_off_c);
    cudaGetSymbolAddress((void**)&cur_r, g_cur_r);
    cudaGetSymbolAddress((void**)&cur_c, g_cur_c);
    cudaGetSymbolAddress((void**)&csr_r, g_csr_r);
    cudaGetSymbolAddress((void**)&csr_c, g_csr_c);

    bf16 *aggr_h, *aggr_l, *aggc_h, *aggc_l, *rowg_h, *rowg_l, *colg_h, *colg_l;
    bf16 *Wr_h, *Wr_l, *Wc_h, *Wc_l, *Wrs_h, *Wrs_l, *Wcs_h, *Wcs_l;
    bf16 *Wmt_h, *Wmt_l, *Wmb_h, *Wmb_l;
    cudaGetSymbolAddress((void**)&aggr_h, g_aggr_h);
    cudaGetSymbolAddress((void**)&aggr_l, g_aggr_l);
    cudaGetSymbolAddress((void**)&aggc_h, g_aggc_h);
    cudaGetSymbolAddress((void**)&aggc_l, g_aggc_l);
    cudaGetSymbolAddress((void**)&rowg_h, g_rowg_h);
    cudaGetSymbolAddress((void**)&rowg_l, g_rowg_l);
    cudaGetSymbolAddress((void**)&colg_h, g_colg_h);
    cudaGetSymbolAddress((void**)&colg_l, g_colg_l);
    cudaGetSymbolAddress((void**)&Wr_h,  g_Wr_h);   cudaGetSymbolAddress((void**)&Wr_l,  g_Wr_l);
    cudaGetSymbolAddress((void**)&Wc_h,  g_Wc_h);   cudaGetSymbolAddress((void**)&Wc_l,  g_Wc_l);
    cudaGetSymbolAddress((void**)&Wrs_h, g_Wrs_h);  cudaGetSymbolAddress((void**)&Wrs_l, g_Wrs_l);
    cudaGetSymbolAddress((void**)&Wcs_h, g_Wcs_h);  cudaGetSymbolAddress((void**)&Wcs_l, g_Wcs_l);
    cudaGetSymbolAddress((void**)&Wmt_h, g_Wmt_h);  cudaGetSymbolAddress((void**)&Wmt_l, g_Wmt_l);
    cudaGetSymbolAddress((void**)&Wmb_h, g_Wmb_h);  cudaGetSymbolAddress((void**)&Wmb_l, g_Wmb_l);

    cudaFuncSetAttribute(gemm_tc2_kernel,
                         cudaFuncAttributeMaxDynamicSharedMemorySize, SMEM_GEMM);

    // graph preprocessing: degrees -> norms -> CSR (row graph first so ncu
    // -s 5 -c 1 captures gather_r as launch #6)
    zero_ideg_kernel<<<(4 * NN + 255) / 256, 256>>>();
    degree_kernel<<<(NE + 255) / 256, 256>>>(er, ec);
    norm_kernel<<<(4 * NN + 255) / 256, 256>>>();
    scan_kernel<<<1, SCAN_T>>>(ideg + 1 * NN, off_r, cur_r);
    fill_kernel<<<(NE + 255) / 256, 256>>>(er, cur_r, csr_r);
    int ggrid = (NN * 32 + 255) / 256;
    gather_kernel<<<ggrid, 256>>>(csr_r, off_r, deg + 0 * NN, deg + 1 * NN, x, aggr_h, aggr_l);
    scan_kernel<<<1, SCAN_T>>>(ideg + 3 * NN, off_c, cur_c);
    fill_kernel<<<(NE + 255) / 256, 256>>>(ec, cur_c, csr_c);
    gather_kernel<<<ggrid, 256>>>(csr_c, off_c, deg + 2 * NN, deg + 3 * NN, x, aggc_h, aggc_l);
    tail_zero_kernel<<<((MP - NN) * KP1 + 255) / 256, 256>>>();

    // weight splits
    int wgrid = (KP1 * NP + 255) / 256;
    w_convert_kernel<<<wgrid, 256>>>(Wr,  DD, DD, Wr_h,  Wr_l);
    w_convert_kernel<<<wgrid, 256>>>(Wc,  DD, DD, Wc_h,  Wc_l);
    w_convert_kernel<<<wgrid, 256>>>(Wrs, DD, DD, Wrs_h, Wrs_l);
    w_convert_kernel<<<wgrid, 256>>>(Wcs, DD, DD, Wcs_h, Wcs_l);
    w_convert_kernel<<<wgrid, 256>>>(Wm,           DD, DD, Wmt_h, Wmt_l);
    w_convert_kernel<<<wgrid, 256>>>(Wm + DD * DD, DD, DD, Wmb_h, Wmb_l);

    dim3 gg(NP / GBN, MP / GBM);   // (5, 782)
    const int nK = KP1 / GBK;      // 10

    // GraphConv GEMMs -> relu -> bf16 planes
    gemm_tc2_kernel<<<gg, 256, SMEM_GEMM>>>(aggr_h, aggr_l, KP1, Wr_h, Wr_l, br,
        NN, DD, nK, 1, 1, 0, nullptr, 0, rowg_h, rowg_l, KP1);
    gemm_tc2_kernel<<<gg, 256, SMEM_GEMM>>>(aggc_h, aggc_l, KP1, Wc_h, Wc_l, bc,
        NN, DD, nK, 1, 1, 0, nullptr, 0, colg_h, colg_l, KP1);

    // support GEMMs -> fp32 merged halves
    gemm_tc2_kernel<<<gg, 256, SMEM_GEMM>>>(rowg_h, rowg_l, KP1, Wrs_h, Wrs_l, brs,
        NN, DD, nK, 0, 0, 0, merged, 2 * DD, nullptr, nullptr, 0);
    gemm_tc2_kernel<<<gg, 256, SMEM_GEMM>>>(colg_h, colg_l, KP1, Wcs_h, Wcs_l, bcs,
        NN, DD, nK, 0, 0, 0, merged + DD, 2 * DD, nullptr, nullptr, 0);

    // LN both halves -> reuse agg plane buffers as merge-GEMM A operands
    int lngrid = (NN + 7) / 8;
    ln_merged_kernel<<<lngrid, 256>>>(merged, g_rs, b_rs, g_cs, b_cs,
                                      aggr_h, aggr_l, aggc_h, aggc_l);

    // merge GEMM as two K=320 passes: out = rowLN@WmTop + bm; out += colLN@WmBot
    gemm_tc2_kernel<<<gg, 256, SMEM_GEMM>>>(aggr_h, aggr_l, KP1, Wmt_h, Wmt_l, bm,
        NN, DD, nK, 0, 0, 0, out, DD, nullptr, nullptr, 0);
    gemm_tc2_kernel<<<gg, 256, SMEM_GEMM>>>(aggc_h, aggc_l, KP1, Wmb_h, Wmb_l, nullptr,
        NN, DD, nK, 0, 0, 1, out, DD, nullptr, nullptr, 0);

    // final LN
    ln_kernel<<<lngrid, 256>>>(out, DD, g_m, b_m, NN);
}

// round 7
// speedup vs baseline: 1.5623x; 1.1639x over previous
#include <cuda_runtime.h>
#include <cuda_bf16.h>
#include <cstddef>
#include <cstdint>

#define NN 100000
#define NE 1000000
#define DD 300
#define MP 100096      // NN padded to 128
#define KP1 320        // K=300 padded
#define NP  320        // N=300 padded

typedef __nv_bfloat16 bf16;
typedef __nv_bfloat162 bf162;

// ---------------- scratch (device globals; no allocation allowed) ----------
__device__ int   g_ideg[4 * NN];              // int degrees [out_r|in_r|out_c|in_c]
__device__ float g_deg[4 * NN];               // rsqrt norms, same layout
__device__ int   g_off_r[NN + 1], g_off_c[NN + 1];
__device__ int   g_cur_r[NN],     g_cur_c[NN];
__device__ int   g_csr_r[NE],     g_csr_c[NE];
__device__ __align__(16) float g_merged[(size_t)NN * 2 * DD];

// parallel-scan temporaries
#define SB 1024
#define NSB ((NN + SB - 1) / SB)   // 98
__device__ int g_bsum[2][NSB];
__device__ int g_boff[2][NSB];

// bf16 hi/lo operand planes (padded, M x K row-major)
__device__ __align__(16) bf16 g_aggr_h[(size_t)MP * KP1];
__device__ __align__(16) bf16 g_aggr_l[(size_t)MP * KP1];
__device__ __align__(16) bf16 g_aggc_h[(size_t)MP * KP1];
__device__ __align__(16) bf16 g_aggc_l[(size_t)MP * KP1];
__device__ __align__(16) bf16 g_rowg_h[(size_t)MP * KP1];
__device__ __align__(16) bf16 g_rowg_l[(size_t)MP * KP1];
__device__ __align__(16) bf16 g_colg_h[(size_t)MP * KP1];
__device__ __align__(16) bf16 g_colg_l[(size_t)MP * KP1];
// weight planes: K x N row-major (KP1 x NP)
__device__ __align__(16) bf16 g_Wr_h[KP1 * NP],  g_Wr_l[KP1 * NP];
__device__ __align__(16) bf16 g_Wc_h[KP1 * NP],  g_Wc_l[KP1 * NP];
__device__ __align__(16) bf16 g_Wrs_h[KP1 * NP], g_Wrs_l[KP1 * NP];
__device__ __align__(16) bf16 g_Wcs_h[KP1 * NP], g_Wcs_l[KP1 * NP];
__device__ __align__(16) bf16 g_Wmt_h[KP1 * NP], g_Wmt_l[KP1 * NP];
__device__ __align__(16) bf16 g_Wmb_h[KP1 * NP], g_Wmb_l[KP1 * NP];

// ---------------- helpers ----------------------------------------------------
__device__ __forceinline__ void split_bf16(float v, bf16& h, bf16& l) {
    h = __float2bfloat16(v);
    l = __float2bfloat16(v - __bfloat162float(h));
}
__device__ __forceinline__ void cp16(uint32_t dst, const void* src) {
    asm volatile("cp.async.cg.shared.global [%0], [%1], 16;" :: "r"(dst), "l"(src));
}
__device__ __forceinline__ void ldsm_x4(uint32_t& r0, uint32_t& r1, uint32_t& r2, uint32_t& r3,
                                        uint32_t addr) {
    asm volatile("ldmatrix.sync.aligned.m8n8.x4.shared.b16 {%0,%1,%2,%3}, [%4];"
                 : "=r"(r0), "=r"(r1), "=r"(r2), "=r"(r3) : "r"(addr));
}
__device__ __forceinline__ void ldsm_x4_t(uint32_t& r0, uint32_t& r1, uint32_t& r2, uint32_t& r3,
                                          uint32_t addr) {
    asm volatile("ldmatrix.sync.aligned.m8n8.x4.trans.shared.b16 {%0,%1,%2,%3}, [%4];"
                 : "=r"(r0), "=r"(r1), "=r"(r2), "=r"(r3) : "r"(addr));
}
__device__ __forceinline__ void mma_bf16(float* c, const uint32_t* a, const uint32_t* b) {
    asm volatile("mma.sync.aligned.m16n8k16.row.col.f32.bf16.bf16.f32 "
                 "{%0,%1,%2,%3}, {%4,%5,%6,%7}, {%8,%9}, {%0,%1,%2,%3};"
                 : "+f"(c[0]), "+f"(c[1]), "+f"(c[2]), "+f"(c[3])
                 : "r"(a[0]), "r"(a[1]), "r"(a[2]), "r"(a[3]), "r"(b[0]), "r"(b[1]));
}

// ---------------- graph preprocessing ----------------------------------------
__global__ void zero_ideg_kernel() {
    int i = blockIdx.x * blockDim.x + threadIdx.x;
    if (i < 4 * NN) g_ideg[i] = 0;
}

__global__ void degree_kernel(const int* __restrict__ er, const int* __restrict__ ec) {
    int i = blockIdx.x * blockDim.x + threadIdx.x;
    if (i < NE) {
        atomicAdd(&g_ideg[0 * NN + er[i]],      1);
        atomicAdd(&g_ideg[1 * NN + er[NE + i]], 1);
        atomicAdd(&g_ideg[2 * NN + ec[i]],      1);
        atomicAdd(&g_ideg[3 * NN + ec[NE + i]], 1);
    }
}

__global__ void norm_kernel() {
    int i = blockIdx.x * blockDim.x + threadIdx.x;
    if (i < 4 * NN) {
        int d = g_ideg[i];
        g_deg[i] = (d > 0) ? rsqrtf((float)d) : 0.f;
    }
}

// ---- 3-phase parallel exclusive scan of in-degrees (both graphs at once) ----
// phase 1: per-block sums
__global__ __launch_bounds__(SB) void scan1_kernel() {
    int gsel = blockIdx.y;
    const int* deg = g_ideg + (gsel ? 3 : 1) * NN;
    int i = blockIdx.x * SB + threadIdx.x;
    int v = (i < NN) ? deg[i] : 0;
    __shared__ int ws[32];
    #pragma unroll
    for (int o = 16; o > 0; o >>= 1) v += __shfl_xor_sync(0xFFFFFFFFu, v, o);
    if ((threadIdx.x & 31) == 0) ws[threadIdx.x >> 5] = v;
    __syncthreads();
    if (threadIdx.x < 32) {
        int s = (threadIdx.x < SB / 32) ? ws[threadIdx.x] : 0;
        #pragma unroll
        for (int o = 16; o > 0; o >>= 1) s += __shfl_xor_sync(0xFFFFFFFFu, s, o);
        if (threadIdx.x == 0) g_bsum[gsel][blockIdx.x] = s;
    }
}

// phase 2: one small block scans both graphs' 98 block sums (exclusive)
__global__ __launch_bounds__(256) void scan2_kernel(int* __restrict__ off_r,
                                                    int* __restrict__ off_c) {
    __shared__ int ss[2][128];
    int t = threadIdx.x;
    int h = t >> 7;          // graph select
    int j = t & 127;
    int v = (j < NSB) ? g_bsum[h][j] : 0;
    ss[h][j] = v;
    __syncthreads();
    #pragma unroll
    for (int d = 1; d < 128; d <<= 1) {
        int u = (j >= d) ? ss[h][j - d] : 0;
        __syncthreads();
        ss[h][j] += u;
        __syncthreads();
    }
    if (j < NSB) g_boff[h][j] = ss[h][j] - v;   // exclusive
    if (t == 0) { off_r[NN] = NE; off_c[NN] = NE; }
}

// phase 3: per-block exclusive scan + base offset -> off/cur
__global__ __launch_bounds__(SB) void scan3_kernel(int* __restrict__ off_r,
                                                   int* __restrict__ cur_r,
                                                   int* __restrict__ off_c,
                                                   int* __restrict__ cur_c) {
    int gsel = blockIdx.y;
    const int* deg = g_ideg + (gsel ? 3 : 1) * NN;
    int* off = gsel ? off_c : off_r;
    int* cur = gsel ? cur_c : cur_r;
    __shared__ int ss[SB];
    int i = blockIdx.x * SB + threadIdx.x;
    int v = (i < NN) ? deg[i] : 0;
    ss[threadIdx.x] = v;
    __syncthreads();
    #pragma unroll
    for (int d = 1; d < SB; d <<= 1) {
        int u = (threadIdx.x >= d) ? ss[threadIdx.x - d] : 0;
        __syncthreads();
        ss[threadIdx.x] += u;
        __syncthreads();
    }
    if (i < NN) {
        int excl = ss[threadIdx.x] - v + g_boff[gsel][blockIdx.x];
        off[i] = excl;
        cur[i] = excl;
    }
}

__global__ void fill_kernel(const int* __restrict__ edges,
                            int* __restrict__ cur, int* __restrict__ csr) {
    int i = blockIdx.x * blockDim.x + threadIdx.x;
    if (i < NE) {
        int s = edges[i];
        int d = edges[NE + i];
        int pos = atomicAdd(&cur[d], 1);
        csr[pos] = s;
    }
}

// one warp per node: acc = sum_in x[src]*nsrc[src]; out = split(acc*ndst) -> planes
__global__ __launch_bounds__(256) void gather_kernel(
    const int* __restrict__ csr, const int* __restrict__ off,
    const float* __restrict__ nsrc, const float* __restrict__ ndst,
    const float* __restrict__ x,
    bf16* __restrict__ Ah, bf16* __restrict__ Al) {
    int warp = (int)((blockIdx.x * (long)blockDim.x + threadIdx.x) >> 5);
    int lane = threadIdx.x & 31;
    if (warp >= NN) return;
    int o0 = off[warp], o1 = off[warp + 1];
    float acc[10];
    #pragma unroll
    for (int k = 0; k < 10; k++) acc[k] = 0.f;
    for (int j = o0; j < o1; j++) {
        int s = csr[j];
        float ns = nsrc[s];
        const float* xr = x + (size_t)s * DD;
        #pragma unroll
        for (int k = 0; k < 9; k++) acc[k] += xr[lane + 32 * k] * ns;
        if (lane < 12) acc[9] += xr[lane + 288] * ns;
    }
    float nd = ndst[warp];
    size_t orow = (size_t)warp * KP1;
    #pragma unroll
    for (int k = 0; k < 10; k++) {
        int c = lane + 32 * k;
        if (c < DD) {
            bf16 h, l;
            split_bf16(acc[k] * nd, h, l);
            Ah[orow + c] = h;
            Al[orow + c] = l;
        }
    }
    if (lane < 20) {
        bf16 z = __float2bfloat16(0.f);
        Ah[orow + 300 + lane] = z;
        Al[orow + 300 + lane] = z;
    }
}

// zero tail rows [NN, MP) of the agg planes
__global__ void tail_zero_kernel() {
    int i = blockIdx.x * blockDim.x + threadIdx.x;
    const int n = (MP - NN) * KP1;    // 30720
    if (i < n) {
        size_t o = (size_t)NN * KP1 + i;
        bf16 z = __float2bfloat16(0.f);
        g_aggr_h[o] = z; g_aggr_l[o] = z;
        g_aggc_h[o] = z; g_aggc_l[o] = z;
    }
}

// weight (K x Ncols fp32 row-major) -> hi/lo planes (KP1 x NP), zero padded
__global__ void w_convert_kernel(const float* __restrict__ W, int K, int Ncols,
                                 bf16* __restrict__ Wh, bf16* __restrict__ Wl) {
    int idx = blockIdx.x * blockDim.x + threadIdx.x;
    if (idx >= KP1 * NP) return;
    int k = idx / NP;
    int n = idx - k * NP;
    float v = (k < K && n < Ncols) ? W[(size_t)k * Ncols + n] : 0.f;
    bf16 h, l;
    split_bf16(v, h, l);
    Wh[idx] = h; Wl[idx] = l;
}

// ================= Tensor-core GEMM (R3 structure, + accum) =================
#define GBM 128
#define GBN 64
#define GBK 32
#define ASTR 40            // halves per A smem row (32 + 8 pad)
#define BSTR 72            // halves per B smem row (64 + 8 pad)
#define A_STAGE_B (GBM * ASTR * 2)   // 10240 bytes
#define B_STAGE_B (GBK * BSTR * 2)   // 4608 bytes
#define SMEM_GEMM (2 * (2 * A_STAGE_B + 2 * B_STAGE_B))  // 59392

__global__ __launch_bounds__(256) void gemm_tc2_kernel(
    const bf16* __restrict__ Aph, const bf16* __restrict__ Apl, int lda,
    const bf16* __restrict__ Bph, const bf16* __restrict__ Bpl,
    const float* __restrict__ bias,
    int M, int Ncols, int nK, int mode, int relu, int accum,
    float* __restrict__ Cf, int ldc,
    bf16* __restrict__ Ch, bf16* __restrict__ Cl, int ldcp)
{
    extern __shared__ __align__(16) char smem[];
    const uint32_t sAh = (uint32_t)__cvta_generic_to_shared(smem);
    const uint32_t sAl = sAh + 2 * A_STAGE_B;
    const uint32_t sBh = sAl + 2 * A_STAGE_B;
    const uint32_t sBl = sBh + 2 * B_STAGE_B;

    const int t = threadIdx.x;
    const int wid = t >> 5;
    const int lane = t & 31;
    const int warp_m = wid >> 1;
    const int warp_n = wid & 1;
    const int m0 = blockIdx.y * GBM;
    const int n0 = blockIdx.x * GBN;

    float acc[2][4][4];
    #pragma unroll
    for (int mi = 0; mi < 2; mi++)
        #pragma unroll
        for (int ni = 0; ni < 4; ni++)
            #pragma unroll
            for (int j = 0; j < 4; j++) acc[mi][ni][j] = 0.f;

    const int ar = t >> 2;
    const int ac = t & 3;
    const int br = t >> 3;
    const int bc = t & 7;

    auto load_stage = [&](int stage, int k0) {
        uint32_t asoff = (uint32_t)stage * A_STAGE_B;
        uint32_t bsoff = (uint32_t)stage * B_STAGE_B;
        #pragma unroll
        for (int i = 0; i < 2; i++) {
            int r = ar + i * 64;
            uint32_t d = asoff + (uint32_t)(r * ASTR + ac * 8) * 2;
            size_t s = (size_t)(m0 + r) * lda + k0 + ac * 8;
            cp16(sAh + d, Aph + s);
            cp16(sAl + d, Apl + s);
        }
        {
            uint32_t d = bsoff + (uint32_t)(br * BSTR + bc * 8) * 2;
            size_t s = (size_t)(k0 + br) * NP + n0 + bc * 8;
            cp16(sBh + d, Bph + s);
            cp16(sBl + d, Bpl + s);
        }
        asm volatile("cp.async.commit_group;");
    };

    load_stage(0, 0);

    const int lrow = lane & 15;
    const int lcol8 = (lane >> 4) << 3;

    for (int kt = 0; kt < nK; kt++) {
        if (kt + 1 < nK) {
            load_stage((kt + 1) & 1, (kt + 1) * GBK);
            asm volatile("cp.async.wait_group 1;");
        } else {
            asm volatile("cp.async.wait_group 0;");
        }
        __syncthreads();

        const int stage = kt & 1;
        const uint32_t aoff = (uint32_t)stage * A_STAGE_B;
        const uint32_t boff = (uint32_t)stage * B_STAGE_B;

        #pragma unroll
        for (int ks = 0; ks < 2; ks++) {
            uint32_t ah[2][4], al[2][4];
            #pragma unroll
            for (int mi = 0; mi < 2; mi++) {
                int row = warp_m * 32 + mi * 16 + lrow;
                int col = ks * 16 + lcol8;
                uint32_t off = aoff + (uint32_t)(row * ASTR + col) * 2;
                ldsm_x4(ah[mi][0], ah[mi][1], ah[mi][2], ah[mi][3], sAh + off);
                ldsm_x4(al[mi][0], al[mi][1], al[mi][2], al[mi][3], sAl + off);
            }
            uint32_t bh[4][2], bl[4][2];
            #pragma unroll
            for (int nj = 0; nj < 2; nj++) {
                int row = ks * 16 + lrow;
                int col = warp_n * 32 + nj * 16 + lcol8;
                uint32_t off = boff + (uint32_t)(row * BSTR + col) * 2;
                uint32_t r0, r1, r2, r3;
                ldsm_x4_t(r0, r1, r2, r3, sBh + off);
                bh[nj * 2 + 0][0] = r0; bh[nj * 2 + 0][1] = r1;
                bh[nj * 2 + 1][0] = r2; bh[nj * 2 + 1][1] = r3;
                ldsm_x4_t(r0, r1, r2, r3, sBl + off);
                bl[nj * 2 + 0][0] = r0; bl[nj * 2 + 0][1] = r1;
                bl[nj * 2 + 1][0] = r2; bl[nj * 2 + 1][1] = r3;
            }
            #pragma unroll
            for (int mi = 0; mi < 2; mi++)
                #pragma unroll
                for (int ni = 0; ni < 4; ni++) {
                    mma_bf16(acc[mi][ni], ah[mi], bh[ni]);
                    mma_bf16(acc[mi][ni], ah[mi], bl[ni]);
                    mma_bf16(acc[mi][ni], al[mi], bh[ni]);
                }
        }
        __syncthreads();
    }

    // ---- epilogue ----
    const int g = lane >> 2;
    const int tig = lane & 3;
    #pragma unroll
    for (int mi = 0; mi < 2; mi++) {
        #pragma unroll
        for (int ni = 0; ni < 4; ni++) {
            int col = n0 + warp_n * 32 + ni * 8 + tig * 2;
            float bx = 0.f, by = 0.f;
            if (bias != nullptr && col < Ncols) {
                bx = bias[col];
                if (col + 1 < Ncols) by = bias[col + 1];
            }
            #pragma unroll
            for (int rr = 0; rr < 2; rr++) {
                int row = m0 + warp_m * 32 + mi * 16 + g + rr * 8;
                float vx = acc[mi][ni][rr * 2 + 0] + bx;
                float vy = acc[mi][ni][rr * 2 + 1] + by;
                if (relu) { vx = fmaxf(vx, 0.f); vy = fmaxf(vy, 0.f); }
                if (mode == 0) {
                    if (row < M && col < Ncols) {
                        float* p = Cf + (size_t)row * ldc + col;
                        if (accum) {
                            float2 old = *(float2*)p;
                            vx += old.x; vy += old.y;
                        }
                        *(float2*)p = make_float2(vx, vy);
                    }
                } else {
                    bool ok = (row < M) && (col < Ncols);
                    if (!ok) { vx = 0.f; vy = 0.f; }
                    bf16 hx, lx, hy, ly;
                    split_bf16(vx, hx, lx);
                    split_bf16(vy, hy, ly);
                    size_t o = (size_t)row * ldcp + col;
                    *(bf162*)&Ch[o] = bf162(hx, hy);
                    *(bf162*)&Cl[o] = bf162(lx, ly);
                }
            }
        }
    }
}

// ---------------- LayerNorm (fp32, in place) --------------------------------
__global__ void ln_kernel(float* __restrict__ X, int ld,
                          const float* __restrict__ gamma,
                          const float* __restrict__ beta, int M) {
    int warp = (int)((blockIdx.x * (long)blockDim.x + threadIdx.x) >> 5);
    int lane = threadIdx.x & 31;
    if (warp >= M) return;
    float* p = X + (size_t)warp * ld;
    float v[10];
    float sum = 0.f;
    #pragma unroll
    for (int k = 0; k < 10; k++) {
        int c = lane + 32 * k;
        v[k] = (c < DD) ? p[c] : 0.f;
        sum += v[k];
    }
    #pragma unroll
    for (int o = 16; o > 0; o >>= 1) sum += __shfl_xor_sync(0xFFFFFFFFu, sum, o);
    float mu = sum * (1.f / DD);
    float var = 0.f;
    #pragma unroll
    for (int k = 0; k < 10; k++) {
        int c = lane + 32 * k;
        float d = (c < DD) ? (v[k] - mu) : 0.f;
        var += d * d;
    }
    #pragma unroll
    for (int o = 16; o > 0; o >>= 1) var += __shfl_xor_sync(0xFFFFFFFFu, var, o);
    float rsig = rsqrtf(var * (1.f / DD) + 1e-5f);
    #pragma unroll
    for (int k = 0; k < 10; k++) {
        int c = lane + 32 * k;
        if (c < DD) p[c] = (v[k] - mu) * rsig * gamma[c] + beta[c];
    }
}

// LN both halves of merged row -> two bf16 hi/lo plane pairs (MP x KP1)
__global__ void ln_merged_kernel(const float* __restrict__ merged,
                                 const float* __restrict__ g0, const float* __restrict__ b0,
                                 const float* __restrict__ g1, const float* __restrict__ b1,
                                 bf16* __restrict__ R_h, bf16* __restrict__ R_l,
                                 bf16* __restrict__ C_h, bf16* __restrict__ C_l) {
    int warp = (int)((blockIdx.x * (long)blockDim.x + threadIdx.x) >> 5);
    int lane = threadIdx.x & 31;
    if (warp >= NN) return;
    const float* prow = merged + (size_t)warp * (2 * DD);
    size_t orow = (size_t)warp * KP1;
    #pragma unroll
    for (int half = 0; half < 2; half++) {
        const float* p = prow + half * DD;
        const float* gamma = half ? g1 : g0;
        const float* beta  = half ? b1 : b0;
        bf16* Dh = half ? C_h : R_h;
        bf16* Dl = half ? C_l : R_l;
        float v[10];
        float sum = 0.f;
        #pragma unroll
        for (int k = 0; k < 10; k++) {
            int c = lane + 32 * k;
            v[k] = (c < DD) ? p[c] : 0.f;
            sum += v[k];
        }
        #pragma unroll
        for (int o = 16; o > 0; o >>= 1) sum += __shfl_xor_sync(0xFFFFFFFFu, sum, o);
        float mu = sum * (1.f / DD);
        float var = 0.f;
        #pragma unroll
        for (int k = 0; k < 10; k++) {
            int c = lane + 32 * k;
            float d = (c < DD) ? (v[k] - mu) : 0.f;
            var += d * d;
        }
        #pragma unroll
        for (int o = 16; o > 0; o >>= 1) var += __shfl_xor_sync(0xFFFFFFFFu, var, o);
        float rsig = rsqrtf(var * (1.f / DD) + 1e-5f);
        #pragma unroll
        for (int k = 0; k < 10; k++) {
            int c = lane + 32 * k;
            if (c < DD) {
                float w = (v[k] - mu) * rsig * gamma[c] + beta[c];
                bf16 h, l;
                split_bf16(w, h, l);
                Dh[orow + c] = h;
                Dl[orow + c] = l;
            }
        }
        if (lane < 20) {
            bf16 z = __float2bfloat16(0.f);
            Dh[orow + 300 + lane] = z;
            Dl[orow + 300 + lane] = z;
        }
    }
}

// ---------------- launch ----------------------------------------------------
extern "C" void kernel_launch(void* const* d_in, const int* in_sizes, int n_in,
                              void* d_out, int out_size) {
    const float* x    = (const float*)d_in[0];
    const int*   er   = (const int*)d_in[1];
    const int*   ec   = (const int*)d_in[2];
    const float* Wr   = (const float*)d_in[3];
    const float* br   = (const float*)d_in[4];
    const float* Wc   = (const float*)d_in[5];
    const float* bc   = (const float*)d_in[6];
    const float* Wrs  = (const float*)d_in[7];
    const float* brs  = (const float*)d_in[8];
    const float* g_rs = (const float*)d_in[9];
    const float* b_rs = (const float*)d_in[10];
    const float* Wcs  = (const float*)d_in[11];
    const float* bcs  = (const float*)d_in[12];
    const float* g_cs = (const float*)d_in[13];
    const float* b_cs = (const float*)d_in[14];
    const float* Wm   = (const float*)d_in[15];
    const float* bm   = (const float*)d_in[16];
    const float* g_m  = (const float*)d_in[17];
    const float* b_m  = (const float*)d_in[18];
    float* out = (float*)d_out;

    float *deg, *merged;
    cudaGetSymbolAddress((void**)&deg,    g_deg);
    cudaGetSymbolAddress((void**)&merged, g_merged);
    int *off_r, *off_c, *cur_r, *cur_c, *csr_r, *csr_c;
    cudaGetSymbolAddress((void**)&off_r, g_off_r);
    cudaGetSymbolAddress((void**)&off_c, g_off_c);
    cudaGetSymbolAddress((void**)&cur_r, g_cur_r);
    cudaGetSymbolAddress((void**)&cur_c, g_cur_c);
    cudaGetSymbolAddress((void**)&csr_r, g_csr_r);
    cudaGetSymbolAddress((void**)&csr_c, g_csr_c);

    bf16 *aggr_h, *aggr_l, *aggc_h, *aggc_l, *rowg_h, *rowg_l, *colg_h, *colg_l;
    bf16 *Wr_h, *Wr_l, *Wc_h, *Wc_l, *Wrs_h, *Wrs_l, *Wcs_h, *Wcs_l;
    bf16 *Wmt_h, *Wmt_l, *Wmb_h, *Wmb_l;
    cudaGetSymbolAddress((void**)&aggr_h, g_aggr_h);
    cudaGetSymbolAddress((void**)&aggr_l, g_aggr_l);
    cudaGetSymbolAddress((void**)&aggc_h, g_aggc_h);
    cudaGetSymbolAddress((void**)&aggc_l, g_aggc_l);
    cudaGetSymbolAddress((void**)&rowg_h, g_rowg_h);
    cudaGetSymbolAddress((void**)&rowg_l, g_rowg_l);
    cudaGetSymbolAddress((void**)&colg_h, g_colg_h);
    cudaGetSymbolAddress((void**)&colg_l, g_colg_l);
    cudaGetSymbolAddress((void**)&Wr_h,  g_Wr_h);   cudaGetSymbolAddress((void**)&Wr_l,  g_Wr_l);
    cudaGetSymbolAddress((void**)&Wc_h,  g_Wc_h);   cudaGetSymbolAddress((void**)&Wc_l,  g_Wc_l);
    cudaGetSymbolAddress((void**)&Wrs_h, g_Wrs_h);  cudaGetSymbolAddress((void**)&Wrs_l, g_Wrs_l);
    cudaGetSymbolAddress((void**)&Wcs_h, g_Wcs_h);  cudaGetSymbolAddress((void**)&Wcs_l, g_Wcs_l);
    cudaGetSymbolAddress((void**)&Wmt_h, g_Wmt_h);  cudaGetSymbolAddress((void**)&Wmt_l, g_Wmt_l);
    cudaGetSymbolAddress((void**)&Wmb_h, g_Wmb_h);  cudaGetSymbolAddress((void**)&Wmb_l, g_Wmb_l);

    cudaFuncSetAttribute(gemm_tc2_kernel,
                         cudaFuncAttributeMaxDynamicSharedMemorySize, SMEM_GEMM);

    // graph preprocessing: degrees -> norms -> parallel scan -> CSR
    zero_ideg_kernel<<<(4 * NN + 255) / 256, 256>>>();
    degree_kernel<<<(NE + 255) / 256, 256>>>(er, ec);
    norm_kernel<<<(4 * NN + 255) / 256, 256>>>();
    dim3 sgrid(NSB, 2);
    scan1_kernel<<<sgrid, SB>>>();
    scan2_kernel<<<1, 256>>>(off_r, off_c);
    scan3_kernel<<<sgrid, SB>>>(off_r, cur_r, off_c, cur_c);
    fill_kernel<<<(NE + 255) / 256, 256>>>(er, cur_r, csr_r);
    fill_kernel<<<(NE + 255) / 256, 256>>>(ec, cur_c, csr_c);
    int ggrid = (NN * 32 + 255) / 256;
    gather_kernel<<<ggrid, 256>>>(csr_r, off_r, deg + 0 * NN, deg + 1 * NN, x, aggr_h, aggr_l);
    gather_kernel<<<ggrid, 256>>>(csr_c, off_c, deg + 2 * NN, deg + 3 * NN, x, aggc_h, aggc_l);
    tail_zero_kernel<<<((MP - NN) * KP1 + 255) / 256, 256>>>();

    // weight splits
    int wgrid = (KP1 * NP + 255) / 256;
    w_convert_kernel<<<wgrid, 256>>>(Wr,  DD, DD, Wr_h,  Wr_l);
    w_convert_kernel<<<wgrid, 256>>>(Wc,  DD, DD, Wc_h,  Wc_l);
    w_convert_kernel<<<wgrid, 256>>>(Wrs, DD, DD, Wrs_h, Wrs_l);
    w_convert_kernel<<<wgrid, 256>>>(Wcs, DD, DD, Wcs_h, Wcs_l);
    w_convert_kernel<<<wgrid, 256>>>(Wm,           DD, DD, Wmt_h, Wmt_l);
    w_convert_kernel<<<wgrid, 256>>>(Wm + DD * DD, DD, DD, Wmb_h, Wmb_l);

    dim3 gg(NP / GBN, MP / GBM);   // (5, 782)
    const int nK = KP1 / GBK;      // 10

    // GraphConv GEMMs -> relu -> bf16 planes
    gemm_tc2_kernel<<<gg, 256, SMEM_GEMM>>>(aggr_h, aggr_l, KP1, Wr_h, Wr_l, br,
        NN, DD, nK, 1, 1, 0, nullptr, 0, rowg_h, rowg_l, KP1);
    gemm_tc2_kernel<<<gg, 256, SMEM_GEMM>>>(aggc_h, aggc_l, KP1, Wc_h, Wc_l, bc,
        NN, DD, nK, 1, 1, 0, nullptr, 0, colg_h, colg_l, KP1);

    // support GEMMs -> fp32 merged halves
    gemm_tc2_kernel<<<gg, 256, SMEM_GEMM>>>(rowg_h, rowg_l, KP1, Wrs_h, Wrs_l, brs,
        NN, DD, nK, 0, 0, 0, merged, 2 * DD, nullptr, nullptr, 0);
    gemm_tc2_kernel<<<gg, 256, SMEM_GEMM>>>(colg_h, colg_l, KP1, Wcs_h, Wcs_l, bcs,
        NN, DD, nK, 0, 0, 0, merged + DD, 2 * DD, nullptr, nullptr, 0);

    // LN both halves -> reuse agg plane buffers as merge-GEMM A operands
    int lngrid = (NN + 7) / 8;
    ln_merged_kernel<<<lngrid, 256>>>(merged, g_rs, b_rs, g_cs, b_cs,
                                      aggr_h, aggr_l, aggc_h, aggc_l);

    // merge GEMM as two K=320 passes: out = rowLN@WmTop + bm; out += colLN@WmBot
    gemm_tc2_kernel<<<gg, 256, SMEM_GEMM>>>(aggr_h, aggr_l, KP1, Wmt_h, Wmt_l, bm,
        NN, DD, nK, 0, 0, 0, out, DD, nullptr, nullptr, 0);
    gemm_tc2_kernel<<<gg, 256, SMEM_GEMM>>>(aggc_h, aggc_l, KP1, Wmb_h, Wmb_l, nullptr,
        NN, DD, nK, 0, 0, 1, out, DD, nullptr, nullptr, 0);

    // final LN
    ln_kernel<<<lngrid, 256>>>(out, DD, g_m, b_m, NN);
}

// round 8
// speedup vs baseline: 1.9195x; 1.2286x over previous
#include <cuda_runtime.h>
#include <cuda_bf16.h>
#include <cstddef>
#include <cstdint>

#define NN 100000
#define NE 1000000
#define DD 300
#define MP 100096      // NN padded to 128
#define KP1 320        // K=300 padded
#define NP  320        // N=300 padded
#define KPM 640        // merge K=600 padded

typedef __nv_bfloat16 bf16;
typedef __nv_bfloat162 bf162;

// ---------------- scratch (device globals; no allocation allowed) ----------
__device__ int   g_ideg[4 * NN];
__device__ float g_deg[4 * NN];
__device__ int   g_off_r[NN + 1], g_off_c[NN + 1];
__device__ int   g_cur_r[NN],     g_cur_c[NN];
__device__ int   g_csr_r[NE],     g_csr_c[NE];
__device__ __align__(16) float g_merged[(size_t)NN * 2 * DD];

#define SB 1024
#define NSB ((NN + SB - 1) / SB)   // 98
__device__ int g_bsum[2][NSB];
__device__ int g_boff[2][NSB];

// bf16 hi/lo operand planes (padded, M x K row-major)
__device__ __align__(16) bf16 g_aggr_h[(size_t)MP * KP1];
__device__ __align__(16) bf16 g_aggr_l[(size_t)MP * KP1];
__device__ __align__(16) bf16 g_aggc_h[(size_t)MP * KP1];
__device__ __align__(16) bf16 g_aggc_l[(size_t)MP * KP1];
__device__ __align__(16) bf16 g_rowg_h[(size_t)MP * KP1];
__device__ __align__(16) bf16 g_rowg_l[(size_t)MP * KP1];
__device__ __align__(16) bf16 g_colg_h[(size_t)MP * KP1];
__device__ __align__(16) bf16 g_colg_l[(size_t)MP * KP1];
// merged LN planes (MP x 640)
__device__ __align__(16) bf16 g_mrg_h[(size_t)MP * KPM];
__device__ __align__(16) bf16 g_mrg_l[(size_t)MP * KPM];
// weight planes: K x N row-major
__device__ __align__(16) bf16 g_Wr_h[KP1 * NP],  g_Wr_l[KP1 * NP];
__device__ __align__(16) bf16 g_Wc_h[KP1 * NP],  g_Wc_l[KP1 * NP];
__device__ __align__(16) bf16 g_Wrs_h[KP1 * NP], g_Wrs_l[KP1 * NP];
__device__ __align__(16) bf16 g_Wcs_h[KP1 * NP], g_Wcs_l[KP1 * NP];
__device__ __align__(16) bf16 g_Wm_h[KPM * NP],  g_Wm_l[KPM * NP];

// ---------------- helpers ----------------------------------------------------
__device__ __forceinline__ void split_bf16(float v, bf16& h, bf16& l) {
    h = __float2bfloat16(v);
    l = __float2bfloat16(v - __bfloat162float(h));
}
__device__ __forceinline__ uint32_t pack2(bf16 a, bf16 b) {
    bf162 t(a, b);
    return *(uint32_t*)&t;
}
#define SWZ(x) ((x) ^ (((x) >> 3) & 0x70))
__device__ __forceinline__ void cp16(uint32_t dst, const void* src) {
    asm volatile("cp.async.cg.shared.global [%0], [%1], 16;" :: "r"(dst), "l"(src));
}
__device__ __forceinline__ void ldsm_x4(uint32_t& r0, uint32_t& r1, uint32_t& r2, uint32_t& r3,
                                        uint32_t addr) {
    asm volatile("ldmatrix.sync.aligned.m8n8.x4.shared.b16 {%0,%1,%2,%3}, [%4];"
                 : "=r"(r0), "=r"(r1), "=r"(r2), "=r"(r3) : "r"(addr));
}
__device__ __forceinline__ void ldsm_x4_t(uint32_t& r0, uint32_t& r1, uint32_t& r2, uint32_t& r3,
                                          uint32_t addr) {
    asm volatile("ldmatrix.sync.aligned.m8n8.x4.trans.shared.b16 {%0,%1,%2,%3}, [%4];"
                 : "=r"(r0), "=r"(r1), "=r"(r2), "=r"(r3) : "r"(addr));
}
__device__ __forceinline__ void mma_bf16(float* c, const uint32_t* a, const uint32_t* b) {
    asm volatile("mma.sync.aligned.m16n8k16.row.col.f32.bf16.bf16.f32 "
                 "{%0,%1,%2,%3}, {%4,%5,%6,%7}, {%8,%9}, {%0,%1,%2,%3};"
                 : "+f"(c[0]), "+f"(c[1]), "+f"(c[2]), "+f"(c[3])
                 : "r"(a[0]), "r"(a[1]), "r"(a[2]), "r"(a[3]), "r"(b[0]), "r"(b[1]));
}

// ---------------- graph preprocessing ----------------------------------------
__global__ void zero_ideg_kernel() {
    int i = blockIdx.x * blockDim.x + threadIdx.x;
    if (i < 4 * NN) g_ideg[i] = 0;
}

__global__ void degree_kernel(const int* __restrict__ er, const int* __restrict__ ec) {
    int i = blockIdx.x * blockDim.x + threadIdx.x;
    if (i < NE) {
        atomicAdd(&g_ideg[0 * NN + er[i]],      1);
        atomicAdd(&g_ideg[1 * NN + er[NE + i]], 1);
        atomicAdd(&g_ideg[2 * NN + ec[i]],      1);
        atomicAdd(&g_ideg[3 * NN + ec[NE + i]], 1);
    }
}

__global__ void norm_kernel() {
    int i = blockIdx.x * blockDim.x + threadIdx.x;
    if (i < 4 * NN) {
        int d = g_ideg[i];
        g_deg[i] = (d > 0) ? rsqrtf((float)d) : 0.f;
    }
}

__global__ __launch_bounds__(SB) void scan1_kernel() {
    int gsel = blockIdx.y;
    const int* deg = g_ideg + (gsel ? 3 : 1) * NN;
    int i = blockIdx.x * SB + threadIdx.x;
    int v = (i < NN) ? deg[i] : 0;
    __shared__ int ws[32];
    #pragma unroll
    for (int o = 16; o > 0; o >>= 1) v += __shfl_xor_sync(0xFFFFFFFFu, v, o);
    if ((threadIdx.x & 31) == 0) ws[threadIdx.x >> 5] = v;
    __syncthreads();
    if (threadIdx.x < 32) {
        int s = (threadIdx.x < SB / 32) ? ws[threadIdx.x] : 0;
        #pragma unroll
        for (int o = 16; o > 0; o >>= 1) s += __shfl_xor_sync(0xFFFFFFFFu, s, o);
        if (threadIdx.x == 0) g_bsum[gsel][blockIdx.x] = s;
    }
}

__global__ __launch_bounds__(256) void scan2_kernel(int* __restrict__ off_r,
                                                    int* __restrict__ off_c) {
    __shared__ int ss[2][128];
    int t = threadIdx.x;
    int h = t >> 7;
    int j = t & 127;
    int v = (j < NSB) ? g_bsum[h][j] : 0;
    ss[h][j] = v;
    __syncthreads();
    #pragma unroll
    for (int d = 1; d < 128; d <<= 1) {
        int u = (j >= d) ? ss[h][j - d] : 0;
        __syncthreads();
        ss[h][j] += u;
        __syncthreads();
    }
    if (j < NSB) g_boff[h][j] = ss[h][j] - v;
    if (t == 0) { off_r[NN] = NE; off_c[NN] = NE; }
}

__global__ __launch_bounds__(SB) void scan3_kernel(int* __restrict__ off_r,
                                                   int* __restrict__ cur_r,
                                                   int* __restrict__ off_c,
                                                   int* __restrict__ cur_c) {
    int gsel = blockIdx.y;
    const int* deg = g_ideg + (gsel ? 3 : 1) * NN;
    int* off = gsel ? off_c : off_r;
    int* cur = gsel ? cur_c : cur_r;
    __shared__ int ss[SB];
    int i = blockIdx.x * SB + threadIdx.x;
    int v = (i < NN) ? deg[i] : 0;
    ss[threadIdx.x] = v;
    __syncthreads();
    #pragma unroll
    for (int d = 1; d < SB; d <<= 1) {
        int u = (threadIdx.x >= d) ? ss[threadIdx.x - d] : 0;
        __syncthreads();
        ss[threadIdx.x] += u;
        __syncthreads();
    }
    if (i < NN) {
        int excl = ss[threadIdx.x] - v + g_boff[gsel][blockIdx.x];
        off[i] = excl;
        cur[i] = excl;
    }
}

__global__ void fill_kernel(const int* __restrict__ edges,
                            int* __restrict__ cur, int* __restrict__ csr) {
    int i = blockIdx.x * blockDim.x + threadIdx.x;
    if (i < NE) {
        int s = edges[i];
        int d = edges[NE + i];
        int pos = atomicAdd(&cur[d], 1);
        csr[pos] = s;
    }
}

// one warp per node, float4 loads; fuses dst-norm + bf16 hi/lo split
__global__ __launch_bounds__(256) void gather_kernel(
    const int* __restrict__ csr, const int* __restrict__ off,
    const float* __restrict__ nsrc, const float* __restrict__ ndst,
    const float* __restrict__ x,
    bf16* __restrict__ Ah, bf16* __restrict__ Al) {
    int warp = (int)((blockIdx.x * (long)blockDim.x + threadIdx.x) >> 5);
    int lane = threadIdx.x & 31;
    if (warp >= NN) return;
    int o0 = off[warp], o1 = off[warp + 1];
    float4 a0 = make_float4(0.f, 0.f, 0.f, 0.f);
    float4 a1 = a0, a2 = a0;
    for (int j = o0; j < o1; j++) {
        int s = csr[j];
        float ns = nsrc[s];
        const float4* xr = (const float4*)(x + (size_t)s * DD);   // 1200B rows, 16B aligned
        float4 v = xr[lane];
        a0.x += v.x * ns; a0.y += v.y * ns; a0.z += v.z * ns; a0.w += v.w * ns;
        v = xr[32 + lane];
        a1.x += v.x * ns; a1.y += v.y * ns; a1.z += v.z * ns; a1.w += v.w * ns;
        if (lane < 11) {
            v = xr[64 + lane];
            a2.x += v.x * ns; a2.y += v.y * ns; a2.z += v.z * ns; a2.w += v.w * ns;
        }
    }
    float nd = ndst[warp];
    size_t orow = (size_t)warp * KP1;
    auto store4 = [&](float4 a, int f4i) {
        bf16 h0, h1, h2, h3, l0, l1, l2, l3;
        split_bf16(a.x * nd, h0, l0); split_bf16(a.y * nd, h1, l1);
        split_bf16(a.z * nd, h2, l2); split_bf16(a.w * nd, h3, l3);
        uint2 hh = make_uint2(pack2(h0, h1), pack2(h2, h3));
        uint2 ll = make_uint2(pack2(l0, l1), pack2(l2, l3));
        *(uint2*)&Ah[orow + f4i * 4] = hh;
        *(uint2*)&Al[orow + f4i * 4] = ll;
    };
    store4(a0, lane);
    store4(a1, 32 + lane);
    if (lane < 11) store4(a2, 64 + lane);
    if (lane < 20) {
        bf16 z = __float2bfloat16(0.f);
        Ah[orow + 300 + lane] = z;
        Al[orow + 300 + lane] = z;
    }
}

// zero tail rows [NN, MP) of agg + mrg planes
__global__ void tail_zero_kernel() {
    int i = blockIdx.x * blockDim.x + threadIdx.x;
    const int nAgg = (MP - NN) * KP1;    // 30720
    const int nMrg = (MP - NN) * KPM;    // 61440
    bf16 z = __float2bfloat16(0.f);
    if (i < nAgg) {
        size_t o = (size_t)NN * KP1 + i;
        g_aggr_h[o] = z; g_aggr_l[o] = z;
        g_aggc_h[o] = z; g_aggc_l[o] = z;
    }
    if (i < nMrg) {
        size_t o = (size_t)NN * KPM + i;
        g_mrg_h[o] = z; g_mrg_l[o] = z;
    }
}

// weight (K x Ncols fp32) -> hi/lo planes (KPp x NP), zero padded
__global__ void w_convert_kernel(const float* __restrict__ W, int K, int Ncols, int KPp,
                                 bf16* __restrict__ Wh, bf16* __restrict__ Wl) {
    int idx = blockIdx.x * blockDim.x + threadIdx.x;
    if (idx >= KPp * NP) return;
    int k = idx / NP;
    int n = idx - k * NP;
    float v = (k < K && n < Ncols) ? W[(size_t)k * Ncols + n] : 0.f;
    bf16 h, l;
    split_bf16(v, h, l);
    Wh[idx] = h; Wl[idx] = l;
}

// ================= Tensor-core GEMM: GBK=64, SW128-swizzled, 2-stage =========
#define GBM 128
#define GBN 64
#define GBK 64
#define A_PL 16384u                 // 128 rows x 128B, per plane
#define B_PL 8192u                  // 64 rows x 128B, per plane
#define STG (2 * A_PL + 2 * B_PL)   // 49152
#define SMEM_GEMM (2 * STG)         // 98304

__global__ __launch_bounds__(256) void gemm_tc2_kernel(
    const bf16* __restrict__ Aph, const bf16* __restrict__ Apl, int lda,
    const bf16* __restrict__ Bph, const bf16* __restrict__ Bpl,
    const float* __restrict__ bias,
    int M, int Ncols, int nK, int mode, int relu,
    float* __restrict__ Cf, int ldc,
    bf16* __restrict__ Ch, bf16* __restrict__ Cl, int ldcp)
{
    extern __shared__ __align__(128) char smem[];
    const uint32_t sb = (uint32_t)__cvta_generic_to_shared(smem);

    const int t = threadIdx.x;
    const int wid = t >> 5;
    const int lane = t & 31;
    const int warp_m = wid >> 1;
    const int warp_n = wid & 1;
    const int m0 = blockIdx.y * GBM;
    const int n0 = blockIdx.x * GBN;

    float acc[2][4][4];
    #pragma unroll
    for (int mi = 0; mi < 2; mi++)
        #pragma unroll
        for (int ni = 0; ni < 4; ni++)
            #pragma unroll
            for (int j = 0; j < 4; j++) acc[mi][ni][j] = 0.f;

    // loader: A 1024 chunks/plane (4/thread), B 512 chunks/plane (2/thread)
    auto load_stage = [&](int stage, int k0) {
        const uint32_t base = sb + (uint32_t)stage * STG;
        const uint32_t aAh = base;
        const uint32_t aAl = base + A_PL;
        const uint32_t aBh = base + 2 * A_PL;
        const uint32_t aBl = base + 2 * A_PL + B_PL;
        #pragma unroll
        for (int i = 0; i < 4; i++) {
            int idx = i * 256 + t;
            int r = idx >> 3, c = idx & 7;
            uint32_t d = SWZ((uint32_t)(r * 128 + c * 16));
            size_t s = (size_t)(m0 + r) * lda + k0 + c * 8;
            cp16(aAh + d, Aph + s);
            cp16(aAl + d, Apl + s);
        }
        #pragma unroll
        for (int i = 0; i < 2; i++) {
            int idx = i * 256 + t;
            int r = idx >> 3, c = idx & 7;
            uint32_t d = SWZ((uint32_t)(r * 128 + c * 16));
            size_t s = (size_t)(k0 + r) * NP + n0 + c * 8;
            cp16(aBh + d, Bph + s);
            cp16(aBl + d, Bpl + s);
        }
        asm volatile("cp.async.commit_group;");
    };

    load_stage(0, 0);

    const int lrow = lane & 15;
    const int lhi = lane >> 4;        // 0/1

    for (int kt = 0; kt < nK; kt++) {
        if (kt + 1 < nK) {
            load_stage((kt + 1) & 1, (kt + 1) * GBK);
            asm volatile("cp.async.wait_group 1;");
        } else {
            asm volatile("cp.async.wait_group 0;");
        }
        __syncthreads();

        const uint32_t base = sb + (uint32_t)(kt & 1) * STG;
        const uint32_t aAh = base;
        const uint32_t aAl = base + A_PL;
        const uint32_t aBh = base + 2 * A_PL;
        const uint32_t aBl = base + 2 * A_PL + B_PL;

        #pragma unroll
        for (int ks = 0; ks < 4; ks++) {
            uint32_t ah[2][4], al[2][4];
            #pragma unroll
            for (int mi = 0; mi < 2; mi++) {
                int row = warp_m * 32 + mi * 16 + lrow;
                uint32_t off = SWZ((uint32_t)(row * 128 + ks * 32 + lhi * 16));
                ldsm_x4(ah[mi][0], ah[mi][1], ah[mi][2], ah[mi][3], aAh + off);
                ldsm_x4(al[mi][0], al[mi][1], al[mi][2], al[mi][3], aAl + off);
            }
            uint32_t bh[4][2], bl[4][2];
            #pragma unroll
            for (int nj = 0; nj < 2; nj++) {
                int krow = ks * 16 + lrow;
                uint32_t off = SWZ((uint32_t)(krow * 128 + warp_n * 64 + nj * 32 + lhi * 16));
                uint32_t r0, r1, r2, r3;
                ldsm_x4_t(r0, r1, r2, r3, aBh + off);
                bh[nj * 2 + 0][0] = r0; bh[nj * 2 + 0][1] = r1;
                bh[nj * 2 + 1][0] = r2; bh[nj * 2 + 1][1] = r3;
                ldsm_x4_t(r0, r1, r2, r3, aBl + off);
                bl[nj * 2 + 0][0] = r0; bl[nj * 2 + 0][1] = r1;
                bl[nj * 2 + 1][0] = r2; bl[nj * 2 + 1][1] = r3;
            }
            #pragma unroll
            for (int mi = 0; mi < 2; mi++)
                #pragma unroll
                for (int ni = 0; ni < 4; ni++) {
                    mma_bf16(acc[mi][ni], ah[mi], bh[ni]);
                    mma_bf16(acc[mi][ni], ah[mi], bl[ni]);
                    mma_bf16(acc[mi][ni], al[mi], bh[ni]);
                }
        }
        __syncthreads();
    }

    // ---- epilogue ----
    const int g = lane >> 2;
    const int tig = lane & 3;
    #pragma unroll
    for (int mi = 0; mi < 2; mi++) {
        #pragma unroll
        for (int ni = 0; ni < 4; ni++) {
            int col = n0 + warp_n * 32 + ni * 8 + tig * 2;
            float bx = 0.f, by = 0.f;
            if (bias != nullptr && col < Ncols) {
                bx = bias[col];
                if (col + 1 < Ncols) by = bias[col + 1];
            }
            #pragma unroll
            for (int rr = 0; rr < 2; rr++) {
                int row = m0 + warp_m * 32 + mi * 16 + g + rr * 8;
                float vx = acc[mi][ni][rr * 2 + 0] + bx;
                float vy = acc[mi][ni][rr * 2 + 1] + by;
                if (relu) { vx = fmaxf(vx, 0.f); vy = fmaxf(vy, 0.f); }
                if (mode == 0) {
                    if (row < M && col < Ncols)
                        *(float2*)(Cf + (size_t)row * ldc + col) = make_float2(vx, vy);
                } else {
                    bool ok = (row < M) && (col < Ncols);
                    if (!ok) { vx = 0.f; vy = 0.f; }
                    bf16 hx, lx, hy, ly;
                    split_bf16(vx, hx, lx);
                    split_bf16(vy, hy, ly);
                    size_t o = (size_t)row * ldcp + col;
                    *(bf162*)&Ch[o] = bf162(hx, hy);
                    *(bf162*)&Cl[o] = bf162(lx, ly);
                }
            }
        }
    }
}

// ---------------- LayerNorm (fp32, in place) --------------------------------
__global__ void ln_kernel(float* __restrict__ X, int ld,
                          const float* __restrict__ gamma,
                          const float* __restrict__ beta, int M) {
    int warp = (int)((blockIdx.x * (long)blockDim.x + threadIdx.x) >> 5);
    int lane = threadIdx.x & 31;
    if (warp >= M) return;
    float* p = X + (size_t)warp * ld;
    float v[10];
    float sum = 0.f;
    #pragma unroll
    for (int k = 0; k < 10; k++) {
        int c = lane + 32 * k;
        v[k] = (c < DD) ? p[c] : 0.f;
        sum += v[k];
    }
    #pragma unroll
    for (int o = 16; o > 0; o >>= 1) sum += __shfl_xor_sync(0xFFFFFFFFu, sum, o);
    float mu = sum * (1.f / DD);
    float var = 0.f;
    #pragma unroll
    for (int k = 0; k < 10; k++) {
        int c = lane + 32 * k;
        float d = (c < DD) ? (v[k] - mu) : 0.f;
        var += d * d;
    }
    #pragma unroll
    for (int o = 16; o > 0; o >>= 1) var += __shfl_xor_sync(0xFFFFFFFFu, var, o);
    float rsig = rsqrtf(var * (1.f / DD) + 1e-5f);
    #pragma unroll
    for (int k = 0; k < 10; k++) {
        int c = lane + 32 * k;
        if (c < DD) p[c] = (v[k] - mu) * rsig * gamma[c] + beta[c];
    }
}

// LN both halves of merged row -> single 640-wide bf16 hi/lo plane pair
__global__ void ln_merged_kernel(const float* __restrict__ merged,
                                 const float* __restrict__ g0, const float* __restrict__ b0,
                                 const float* __restrict__ g1, const float* __restrict__ b1) {
    int warp = (int)((blockIdx.x * (long)blockDim.x + threadIdx.x) >> 5);
    int lane = threadIdx.x & 31;
    if (warp >= NN) return;
    const float* prow = merged + (size_t)warp * (2 * DD);
    size_t orow = (size_t)warp * KPM;
    #pragma unroll
    for (int half = 0; half < 2; half++) {
        const float* p = prow + half * DD;
        const float* gamma = half ? g1 : g0;
        const float* beta  = half ? b1 : b0;
        float v[10];
        float sum = 0.f;
        #pragma unroll
        for (int k = 0; k < 10; k++) {
            int c = lane + 32 * k;
            v[k] = (c < DD) ? p[c] : 0.f;
            sum += v[k];
        }
        #pragma unroll
        for (int o = 16; o > 0; o >>= 1) sum += __shfl_xor_sync(0xFFFFFFFFu, sum, o);
        float mu = sum * (1.f / DD);
        float var = 0.f;
        #pragma unroll
        for (int k = 0; k < 10; k++) {
            int c = lane + 32 * k;
            float d = (c < DD) ? (v[k] - mu) : 0.f;
            var += d * d;
        }
        #pragma unroll
        for (int o = 16; o > 0; o >>= 1) var += __shfl_xor_sync(0xFFFFFFFFu, var, o);
        float rsig = rsqrtf(var * (1.f / DD) + 1e-5f);
        #pragma unroll
        for (int k = 0; k < 10; k++) {
            int c = lane + 32 * k;
            if (c < DD) {
                float w = (v[k] - mu) * rsig * gamma[c] + beta[c];
                bf16 h, l;
                split_bf16(w, h, l);
                g_mrg_h[orow + half * DD + c] = h;
                g_mrg_l[orow + half * DD + c] = l;
            }
        }
    }
    // zero pad cols [600, 640)
    bf16 z = __float2bfloat16(0.f);
    g_mrg_h[orow + 600 + lane] = z;
    g_mrg_l[orow + 600 + lane] = z;
    if (lane < 8) {
        g_mrg_h[orow + 632 + lane] = z;
        g_mrg_l[orow + 632 + lane] = z;
    }
}

// ---------------- launch ----------------------------------------------------
extern "C" void kernel_launch(void* const* d_in, const int* in_sizes, int n_in,
                              void* d_out, int out_size) {
    const float* x    = (const float*)d_in[0];
    const int*   er   = (const int*)d_in[1];
    const int*   ec   = (const int*)d_in[2];
    const float* Wr   = (const float*)d_in[3];
    const float* br   = (const float*)d_in[4];
    const float* Wc   = (const float*)d_in[5];
    const float* bc   = (const float*)d_in[6];
    const float* Wrs  = (const float*)d_in[7];
    const float* brs  = (const float*)d_in[8];
    const float* g_rs = (const float*)d_in[9];
    const float* b_rs = (const float*)d_in[10];
    const float* Wcs  = (const float*)d_in[11];
    const float* bcs  = (const float*)d_in[12];
    const float* g_cs = (const float*)d_in[13];
    const float* b_cs = (const float*)d_in[14];
    const float* Wm   = (const float*)d_in[15];
    const float* bm   = (const float*)d_in[16];
    const float* g_m  = (const float*)d_in[17];
    const float* b_m  = (const float*)d_in[18];
    float* out = (float*)d_out;

    float *deg, *merged;
    cudaGetSymbolAddress((void**)&deg,    g_deg);
    cudaGetSymbolAddress((void**)&merged, g_merged);
    int *off_r, *off_c, *cur_r, *cur_c, *csr_r, *csr_c;
    cudaGetSymbolAddress((void**)&off_r, g_off_r);
    cudaGetSymbolAddress((void**)&off_c, g_off_c);
    cudaGetSymbolAddress((void**)&cur_r, g_cur_r);
    cudaGetSymbolAddress((void**)&cur_c, g_cur_c);
    cudaGetSymbolAddress((void**)&csr_r, g_csr_r);
    cudaGetSymbolAddress((void**)&csr_c, g_csr_c);

    bf16 *aggr_h, *aggr_l, *aggc_h, *aggc_l, *rowg_h, *rowg_l, *colg_h, *colg_l;
    bf16 *mrg_h, *mrg_l;
    bf16 *Wr_h, *Wr_l, *Wc_h, *Wc_l, *Wrs_h, *Wrs_l, *Wcs_h, *Wcs_l, *Wm_h, *Wm_l;
    cudaGetSymbolAddress((void**)&aggr_h, g_aggr_h);
    cudaGetSymbolAddress((void**)&aggr_l, g_aggr_l);
    cudaGetSymbolAddress((void**)&aggc_h, g_aggc_h);
    cudaGetSymbolAddress((void**)&aggc_l, g_aggc_l);
    cudaGetSymbolAddress((void**)&rowg_h, g_rowg_h);
    cudaGetSymbolAddress((void**)&rowg_l, g_rowg_l);
    cudaGetSymbolAddress((void**)&colg_h, g_colg_h);
    cudaGetSymbolAddress((void**)&colg_l, g_colg_l);
    cudaGetSymbolAddress((void**)&mrg_h,  g_mrg_h);
    cudaGetSymbolAddress((void**)&mrg_l,  g_mrg_l);
    cudaGetSymbolAddress((void**)&Wr_h,  g_Wr_h);   cudaGetSymbolAddress((void**)&Wr_l,  g_Wr_l);
    cudaGetSymbolAddress((void**)&Wc_h,  g_Wc_h);   cudaGetSymbolAddress((void**)&Wc_l,  g_Wc_l);
    cudaGetSymbolAddress((void**)&Wrs_h, g_Wrs_h);  cudaGetSymbolAddress((void**)&Wrs_l, g_Wrs_l);
    cudaGetSymbolAddress((void**)&Wcs_h, g_Wcs_h);  cudaGetSymbolAddress((void**)&Wcs_l, g_Wcs_l);
    cudaGetSymbolAddress((void**)&Wm_h,  g_Wm_h);   cudaGetSymbolAddress((void**)&Wm_l,  g_Wm_l);

    cudaFuncSetAttribute(gemm_tc2_kernel,
                         cudaFuncAttributeMaxDynamicSharedMemorySize, SMEM_GEMM);

    // graph preprocessing
    zero_ideg_kernel<<<(4 * NN + 255) / 256, 256>>>();
    degree_kernel<<<(NE + 255) / 256, 256>>>(er, ec);
    norm_kernel<<<(4 * NN + 255) / 256, 256>>>();
    dim3 sgrid(NSB, 2);
    scan1_kernel<<<sgrid, SB>>>();
    scan2_kernel<<<1, 256>>>(off_r, off_c);
    scan3_kernel<<<sgrid, SB>>>(off_r, cur_r, off_c, cur_c);
    fill_kernel<<<(NE + 255) / 256, 256>>>(er, cur_r, csr_r);
    fill_kernel<<<(NE + 255) / 256, 256>>>(ec, cur_c, csr_c);
    int ggrid = (NN * 32 + 255) / 256;
    gather_kernel<<<ggrid, 256>>>(csr_r, off_r, deg + 0 * NN, deg + 1 * NN, x, aggr_h, aggr_l);
    gather_kernel<<<ggrid, 256>>>(csr_c, off_c, deg + 2 * NN, deg + 3 * NN, x, aggc_h, aggc_l);
    tail_zero_kernel<<<((MP - NN) * KPM + 255) / 256, 256>>>();

    // weight splits
    int wgrid = (KP1 * NP + 255) / 256;
    w_convert_kernel<<<wgrid, 256>>>(Wr,  DD, DD, KP1, Wr_h,  Wr_l);
    w_convert_kernel<<<wgrid, 256>>>(Wc,  DD, DD, KP1, Wc_h,  Wc_l);
    w_convert_kernel<<<wgrid, 256>>>(Wrs, DD, DD, KP1, Wrs_h, Wrs_l);
    w_convert_kernel<<<wgrid, 256>>>(Wcs, DD, DD, KP1, Wcs_h, Wcs_l);
    w_convert_kernel<<<(KPM * NP + 255) / 256, 256>>>(Wm, 2 * DD, DD, KPM, Wm_h, Wm_l);

    dim3 gg(NP / GBN, MP / GBM);   // (5, 782)
    const int nK1 = KP1 / GBK;     // 5
    const int nKm = KPM / GBK;     // 10

    // GraphConv GEMMs -> relu -> bf16 planes
    gemm_tc2_kernel<<<gg, 256, SMEM_GEMM>>>(aggr_h, aggr_l, KP1, Wr_h, Wr_l, br,
        NN, DD, nK1, 1, 1, nullptr, 0, rowg_h, rowg_l, KP1);
    gemm_tc2_kernel<<<gg, 256, SMEM_GEMM>>>(aggc_h, aggc_l, KP1, Wc_h, Wc_l, bc,
        NN, DD, nK1, 1, 1, nullptr, 0, colg_h, colg_l, KP1);

    // support GEMMs -> fp32 merged halves
    gemm_tc2_kernel<<<gg, 256, SMEM_GEMM>>>(rowg_h, rowg_l, KP1, Wrs_h, Wrs_l, brs,
        NN, DD, nK1, 0, 0, merged, 2 * DD, nullptr, nullptr, 0);
    gemm_tc2_kernel<<<gg, 256, SMEM_GEMM>>>(colg_h, colg_l, KP1, Wcs_h, Wcs_l, bcs,
        NN, DD, nK1, 0, 0, merged + DD, 2 * DD, nullptr, nullptr, 0);

    // LN both halves -> 640-wide mrg planes
    int lngrid = (NN + 7) / 8;
    ln_merged_kernel<<<lngrid, 256>>>(merged, g_rs, b_rs, g_cs, b_cs);

    // merge GEMM (K=640) -> fp32 out, then final LN
    gemm_tc2_kernel<<<gg, 256, SMEM_GEMM>>>(mrg_h, mrg_l, KPM, Wm_h, Wm_l, bm,
        NN, DD, nKm, 0, 0, out, DD, nullptr, nullptr, 0);
    ln_kernel<<<lngrid, 256>>>(out, DD, g_m, b_m, NN);
}

// round 9
// speedup vs baseline: 2.2778x; 1.1867x over previous
#include <cuda_runtime.h>
#include <cuda_fp16.h>
#include <cstddef>
#include <cstdint>

#define NN 100000
#define NE 1000000
#define DD 300
#define MP 100096      // NN padded to 128
#define KP1 320        // K=300 padded
#define NP  320        // N=300 padded
#define KPM 640        // merge K=600 padded

typedef __half fp16;
typedef __half2 fp162;

// ---------------- scratch (device globals; no allocation allowed) ----------
__device__ int   g_ideg[4 * NN];
__device__ float g_deg[4 * NN];
__device__ int   g_off_r[NN + 1], g_off_c[NN + 1];
__device__ int   g_cur_r[NN],     g_cur_c[NN];
__device__ int   g_csr_r[NE],     g_csr_c[NE];
__device__ __align__(16) float g_merged[(size_t)NN * 2 * DD];

#define SB 1024
#define NSB ((NN + SB - 1) / SB)   // 98
__device__ int g_bsum[2][NSB];
__device__ int g_boff[2][NSB];

// fp16 hi/lo A-operand planes (padded, M x K row-major)
__device__ __align__(16) fp16 g_aggr_h[(size_t)MP * KP1];
__device__ __align__(16) fp16 g_aggr_l[(size_t)MP * KP1];
__device__ __align__(16) fp16 g_aggc_h[(size_t)MP * KP1];
__device__ __align__(16) fp16 g_aggc_l[(size_t)MP * KP1];
__device__ __align__(16) fp16 g_rowg_h[(size_t)MP * KP1];
__device__ __align__(16) fp16 g_rowg_l[(size_t)MP * KP1];
__device__ __align__(16) fp16 g_colg_h[(size_t)MP * KP1];
__device__ __align__(16) fp16 g_colg_l[(size_t)MP * KP1];
__device__ __align__(16) fp16 g_mrg_h[(size_t)MP * KPM];
__device__ __align__(16) fp16 g_mrg_l[(size_t)MP * KPM];
// weight planes (single fp16): K x N row-major
__device__ __align__(16) fp16 g_Wr[KP1 * NP];
__device__ __align__(16) fp16 g_Wc[KP1 * NP];
__device__ __align__(16) fp16 g_Wrs[KP1 * NP];
__device__ __align__(16) fp16 g_Wcs[KP1 * NP];
__device__ __align__(16) fp16 g_Wm[KPM * NP];

// ---------------- helpers ----------------------------------------------------
__device__ __forceinline__ void split_fp16(float v, fp16& h, fp16& l) {
    h = __float2half(v);
    l = __float2half(v - __half2float(h));
}
__device__ __forceinline__ uint32_t pack2(fp16 a, fp16 b) {
    fp162 t = __halves2half2(a, b);
    return *(uint32_t*)&t;
}
#define SWZ(x) ((x) ^ (((x) >> 3) & 0x70))
__device__ __forceinline__ void cp16(uint32_t dst, const void* src) {
    asm volatile("cp.async.cg.shared.global [%0], [%1], 16;" :: "r"(dst), "l"(src));
}
__device__ __forceinline__ void ldsm_x4(uint32_t& r0, uint32_t& r1, uint32_t& r2, uint32_t& r3,
                                        uint32_t addr) {
    asm volatile("ldmatrix.sync.aligned.m8n8.x4.shared.b16 {%0,%1,%2,%3}, [%4];"
                 : "=r"(r0), "=r"(r1), "=r"(r2), "=r"(r3) : "r"(addr));
}
__device__ __forceinline__ void ldsm_x4_t(uint32_t& r0, uint32_t& r1, uint32_t& r2, uint32_t& r3,
                                          uint32_t addr) {
    asm volatile("ldmatrix.sync.aligned.m8n8.x4.trans.shared.b16 {%0,%1,%2,%3}, [%4];"
                 : "=r"(r0), "=r"(r1), "=r"(r2), "=r"(r3) : "r"(addr));
}
__device__ __forceinline__ void mma_fp16(float* c, const uint32_t* a, const uint32_t* b) {
    asm volatile("mma.sync.aligned.m16n8k16.row.col.f32.f16.f16.f32 "
                 "{%0,%1,%2,%3}, {%4,%5,%6,%7}, {%8,%9}, {%0,%1,%2,%3};"
                 : "+f"(c[0]), "+f"(c[1]), "+f"(c[2]), "+f"(c[3])
                 : "r"(a[0]), "r"(a[1]), "r"(a[2]), "r"(a[3]), "r"(b[0]), "r"(b[1]));
}

// ---------------- graph preprocessing ----------------------------------------
__global__ void zero_ideg_kernel() {
    int i = blockIdx.x * blockDim.x + threadIdx.x;
    if (i < 4 * NN) g_ideg[i] = 0;
}

__global__ void degree_kernel(const int* __restrict__ er, const int* __restrict__ ec) {
    int i = blockIdx.x * blockDim.x + threadIdx.x;
    if (i < NE) {
        atomicAdd(&g_ideg[0 * NN + er[i]],      1);
        atomicAdd(&g_ideg[1 * NN + er[NE + i]], 1);
        atomicAdd(&g_ideg[2 * NN + ec[i]],      1);
        atomicAdd(&g_ideg[3 * NN + ec[NE + i]], 1);
    }
}

__global__ void norm_kernel() {
    int i = blockIdx.x * blockDim.x + threadIdx.x;
    if (i < 4 * NN) {
        int d = g_ideg[i];
        g_deg[i] = (d > 0) ? rsqrtf((float)d) : 0.f;
    }
}

__global__ __launch_bounds__(SB) void scan1_kernel() {
    int gsel = blockIdx.y;
    const int* deg = g_ideg + (gsel ? 3 : 1) * NN;
    int i = blockIdx.x * SB + threadIdx.x;
    int v = (i < NN) ? deg[i] : 0;
    __shared__ int ws[32];
    #pragma unroll
    for (int o = 16; o > 0; o >>= 1) v += __shfl_xor_sync(0xFFFFFFFFu, v, o);
    if ((threadIdx.x & 31) == 0) ws[threadIdx.x >> 5] = v;
    __syncthreads();
    if (threadIdx.x < 32) {
        int s = (threadIdx.x < SB / 32) ? ws[threadIdx.x] : 0;
        #pragma unroll
        for (int o = 16; o > 0; o >>= 1) s += __shfl_xor_sync(0xFFFFFFFFu, s, o);
        if (threadIdx.x == 0) g_bsum[gsel][blockIdx.x] = s;
    }
}

__global__ __launch_bounds__(256) void scan2_kernel(int* __restrict__ off_r,
                                                    int* __restrict__ off_c) {
    __shared__ int ss[2][128];
    int t = threadIdx.x;
    int h = t >> 7;
    int j = t & 127;
    int v = (j < NSB) ? g_bsum[h][j] : 0;
    ss[h][j] = v;
    __syncthreads();
    #pragma unroll
    for (int d = 1; d < 128; d <<= 1) {
        int u = (j >= d) ? ss[h][j - d] : 0;
        __syncthreads();
        ss[h][j] += u;
        __syncthreads();
    }
    if (j < NSB) g_boff[h][j] = ss[h][j] - v;
    if (t == 0) { off_r[NN] = NE; off_c[NN] = NE; }
}

__global__ __launch_bounds__(SB) void scan3_kernel(int* __restrict__ off_r,
                                                   int* __restrict__ cur_r,
                                                   int* __restrict__ off_c,
                                                   int* __restrict__ cur_c) {
    int gsel = blockIdx.y;
    const int* deg = g_ideg + (gsel ? 3 : 1) * NN;
    int* off = gsel ? off_c : off_r;
    int* cur = gsel ? cur_c : cur_r;
    __shared__ int ss[SB];
    int i = blockIdx.x * SB + threadIdx.x;
    int v = (i < NN) ? deg[i] : 0;
    ss[threadIdx.x] = v;
    __syncthreads();
    #pragma unroll
    for (int d = 1; d < SB; d <<= 1) {
        int u = (threadIdx.x >= d) ? ss[threadIdx.x - d] : 0;
        __syncthreads();
        ss[threadIdx.x] += u;
        __syncthreads();
    }
    if (i < NN) {
        int excl = ss[threadIdx.x] - v + g_boff[gsel][blockIdx.x];
        off[i] = excl;
        cur[i] = excl;
    }
}

__global__ void fill_kernel(const int* __restrict__ edges,
                            int* __restrict__ cur, int* __restrict__ csr) {
    int i = blockIdx.x * blockDim.x + threadIdx.x;
    if (i < NE) {
        int s = edges[i];
        int d = edges[NE + i];
        int pos = atomicAdd(&cur[d], 1);
        csr[pos] = s;
    }
}

// one warp per node, float4 loads; fuses dst-norm + fp16 hi/lo split
__global__ __launch_bounds__(256) void gather_kernel(
    const int* __restrict__ csr, const int* __restrict__ off,
    const float* __restrict__ nsrc, const float* __restrict__ ndst,
    const float* __restrict__ x,
    fp16* __restrict__ Ah, fp16* __restrict__ Al) {
    int warp = (int)((blockIdx.x * (long)blockDim.x + threadIdx.x) >> 5);
    int lane = threadIdx.x & 31;
    if (warp >= NN) return;
    int o0 = off[warp], o1 = off[warp + 1];
    float4 a0 = make_float4(0.f, 0.f, 0.f, 0.f);
    float4 a1 = a0, a2 = a0;
    for (int j = o0; j < o1; j++) {
        int s = csr[j];
        float ns = nsrc[s];
        const float4* xr = (const float4*)(x + (size_t)s * DD);
        float4 v = xr[lane];
        a0.x += v.x * ns; a0.y += v.y * ns; a0.z += v.z * ns; a0.w += v.w * ns;
        v = xr[32 + lane];
        a1.x += v.x * ns; a1.y += v.y * ns; a1.z += v.z * ns; a1.w += v.w * ns;
        if (lane < 11) {
            v = xr[64 + lane];
            a2.x += v.x * ns; a2.y += v.y * ns; a2.z += v.z * ns; a2.w += v.w * ns;
        }
    }
    float nd = ndst[warp];
    size_t orow = (size_t)warp * KP1;
    auto store4 = [&](float4 a, int f4i) {
        fp16 h0, h1, h2, h3, l0, l1, l2, l3;
        split_fp16(a.x * nd, h0, l0); split_fp16(a.y * nd, h1, l1);
        split_fp16(a.z * nd, h2, l2); split_fp16(a.w * nd, h3, l3);
        uint2 hh = make_uint2(pack2(h0, h1), pack2(h2, h3));
        uint2 ll = make_uint2(pack2(l0, l1), pack2(l2, l3));
        *(uint2*)&Ah[orow + f4i * 4] = hh;
        *(uint2*)&Al[orow + f4i * 4] = ll;
    };
    store4(a0, lane);
    store4(a1, 32 + lane);
    if (lane < 11) store4(a2, 64 + lane);
    if (lane < 20) {
        fp16 z = __float2half(0.f);
        Ah[orow + 300 + lane] = z;
        Al[orow + 300 + lane] = z;
    }
}

// zero tail rows [NN, MP) of agg + mrg planes
__global__ void tail_zero_kernel() {
    int i = blockIdx.x * blockDim.x + threadIdx.x;
    const int nAgg = (MP - NN) * KP1;
    const int nMrg = (MP - NN) * KPM;
    fp16 z = __float2half(0.f);
    if (i < nAgg) {
        size_t o = (size_t)NN * KP1 + i;
        g_aggr_h[o] = z; g_aggr_l[o] = z;
        g_aggc_h[o] = z; g_aggc_l[o] = z;
    }
    if (i < nMrg) {
        size_t o = (size_t)NN * KPM + i;
        g_mrg_h[o] = z; g_mrg_l[o] = z;
    }
}

// weight (K x Ncols fp32) -> single fp16 plane (KPp x NP), zero padded
__global__ void w_convert_kernel(const float* __restrict__ W, int K, int Ncols, int KPp,
                                 fp16* __restrict__ Wh) {
    int idx = blockIdx.x * blockDim.x + threadIdx.x;
    if (idx >= KPp * NP) return;
    int k = idx / NP;
    int n = idx - k * NP;
    float v = (k < K && n < Ncols) ? W[(size_t)k * Ncols + n] : 0.f;
    Wh[idx] = __float2half(v);
}

// ================= Tensor-core GEMM: fp16 2-pass, SW128, GBK=64, 2-stage =====
#define GBM 128
#define GBN 64
#define GBK 64
#define A_PL 16384u                 // 128 rows x 128B, per plane
#define B_PL 8192u                  // 64 rows x 128B
#define STG (2 * A_PL + B_PL)       // 40960
#define SMEM_GEMM (2 * STG)         // 81920

__global__ __launch_bounds__(256) void gemm_tc2_kernel(
    const fp16* __restrict__ Aph, const fp16* __restrict__ Apl, int lda,
    const fp16* __restrict__ Bp,
    const float* __restrict__ bias,
    int M, int Ncols, int nK, int mode, int relu,
    float* __restrict__ Cf, int ldc,
    fp16* __restrict__ Ch, fp16* __restrict__ Cl, int ldcp)
{
    extern __shared__ __align__(128) char smem[];
    const uint32_t sb = (uint32_t)__cvta_generic_to_shared(smem);

    const int t = threadIdx.x;
    const int wid = t >> 5;
    const int lane = t & 31;
    const int warp_m = wid >> 1;
    const int warp_n = wid & 1;
    const int m0 = blockIdx.y * GBM;
    const int n0 = blockIdx.x * GBN;

    float acc[2][4][4];
    #pragma unroll
    for (int mi = 0; mi < 2; mi++)
        #pragma unroll
        for (int ni = 0; ni < 4; ni++)
            #pragma unroll
            for (int j = 0; j < 4; j++) acc[mi][ni][j] = 0.f;

    auto load_stage = [&](int stage, int k0) {
        const uint32_t base = sb + (uint32_t)stage * STG;
        const uint32_t aAh = base;
        const uint32_t aAl = base + A_PL;
        const uint32_t aB  = base + 2 * A_PL;
        #pragma unroll
        for (int i = 0; i < 4; i++) {
            int idx = i * 256 + t;
            int r = idx >> 3, c = idx & 7;
            uint32_t d = SWZ((uint32_t)(r * 128 + c * 16));
            size_t s = (size_t)(m0 + r) * lda + k0 + c * 8;
            cp16(aAh + d, Aph + s);
            cp16(aAl + d, Apl + s);
        }
        #pragma unroll
        for (int i = 0; i < 2; i++) {
            int idx = i * 256 + t;
            int r = idx >> 3, c = idx & 7;
            uint32_t d = SWZ((uint32_t)(r * 128 + c * 16));
            size_t s = (size_t)(k0 + r) * NP + n0 + c * 8;
            cp16(aB + d, Bp + s);
        }
        asm volatile("cp.async.commit_group;");
    };

    load_stage(0, 0);

    const int lrow = lane & 15;
    const int lhi = lane >> 4;

    for (int kt = 0; kt < nK; kt++) {
        if (kt + 1 < nK) {
            load_stage((kt + 1) & 1, (kt + 1) * GBK);
            asm volatile("cp.async.wait_group 1;");
        } else {
            asm volatile("cp.async.wait_group 0;");
        }
        __syncthreads();

        const uint32_t base = sb + (uint32_t)(kt & 1) * STG;
        const uint32_t aAh = base;
        const uint32_t aAl = base + A_PL;
        const uint32_t aB  = base + 2 * A_PL;

        #pragma unroll
        for (int ks = 0; ks < 4; ks++) {
            uint32_t ah[2][4], al[2][4];
            #pragma unroll
            for (int mi = 0; mi < 2; mi++) {
                int row = warp_m * 32 + mi * 16 + lrow;
                uint32_t off = SWZ((uint32_t)(row * 128 + ks * 32 + lhi * 16));
                ldsm_x4(ah[mi][0], ah[mi][1], ah[mi][2], ah[mi][3], aAh + off);
                ldsm_x4(al[mi][0], al[mi][1], al[mi][2], al[mi][3], aAl + off);
            }
            uint32_t bh[4][2];
            #pragma unroll
            for (int nj = 0; nj < 2; nj++) {
                int krow = ks * 16 + lrow;
                uint32_t off = SWZ((uint32_t)(krow * 128 + warp_n * 64 + nj * 32 + lhi * 16));
                uint32_t r0, r1, r2, r3;
                ldsm_x4_t(r0, r1, r2, r3, aB + off);
                bh[nj * 2 + 0][0] = r0; bh[nj * 2 + 0][1] = r1;
                bh[nj * 2 + 1][0] = r2; bh[nj * 2 + 1][1] = r3;
            }
            #pragma unroll
            for (int mi = 0; mi < 2; mi++)
                #pragma unroll
                for (int ni = 0; ni < 4; ni++) {
                    mma_fp16(acc[mi][ni], ah[mi], bh[ni]);
                    mma_fp16(acc[mi][ni], al[mi], bh[ni]);
                }
        }
        __syncthreads();
    }

    // ---- epilogue ----
    const int g = lane >> 2;
    const int tig = lane & 3;
    #pragma unroll
    for (int mi = 0; mi < 2; mi++) {
        #pragma unroll
        for (int ni = 0; ni < 4; ni++) {
            int col = n0 + warp_n * 32 + ni * 8 + tig * 2;
            float bx = 0.f, by = 0.f;
            if (bias != nullptr && col < Ncols) {
                bx = bias[col];
                if (col + 1 < Ncols) by = bias[col + 1];
            }
            #pragma unroll
            for (int rr = 0; rr < 2; rr++) {
                int row = m0 + warp_m * 32 + mi * 16 + g + rr * 8;
                float vx = acc[mi][ni][rr * 2 + 0] + bx;
                float vy = acc[mi][ni][rr * 2 + 1] + by;
                if (relu) { vx = fmaxf(vx, 0.f); vy = fmaxf(vy, 0.f); }
                if (mode == 0) {
                    if (row < M && col < Ncols)
                        *(float2*)(Cf + (size_t)row * ldc + col) = make_float2(vx, vy);
                } else {
                    bool ok = (row < M) && (col < Ncols);
                    if (!ok) { vx = 0.f; vy = 0.f; }
                    fp16 hx, lx, hy, ly;
                    split_fp16(vx, hx, lx);
                    split_fp16(vy, hy, ly);
                    size_t o = (size_t)row * ldcp + col;
                    *(uint32_t*)&Ch[o] = pack2(hx, hy);
                    *(uint32_t*)&Cl[o] = pack2(lx, ly);
                }
            }
        }
    }
}

// ---------------- LayerNorm (fp32, in place) --------------------------------
__global__ void ln_kernel(float* __restrict__ X, int ld,
                          const float* __restrict__ gamma,
                          const float* __restrict__ beta, int M) {
    int warp = (int)((blockIdx.x * (long)blockDim.x + threadIdx.x) >> 5);
    int lane = threadIdx.x & 31;
    if (warp >= M) return;
    float* p = X + (size_t)warp * ld;
    float v[10];
    float sum = 0.f;
    #pragma unroll
    for (int k = 0; k < 10; k++) {
        int c = lane + 32 * k;
        v[k] = (c < DD) ? p[c] : 0.f;
        sum += v[k];
    }
    #pragma unroll
    for (int o = 16; o > 0; o >>= 1) sum += __shfl_xor_sync(0xFFFFFFFFu, sum, o);
    float mu = sum * (1.f / DD);
    float var = 0.f;
    #pragma unroll
    for (int k = 0; k < 10; k++) {
        int c = lane + 32 * k;
        float d = (c < DD) ? (v[k] - mu) : 0.f;
        var += d * d;
    }
    #pragma unroll
    for (int o = 16; o > 0; o >>= 1) var += __shfl_xor_sync(0xFFFFFFFFu, var, o);
    float rsig = rsqrtf(var * (1.f / DD) + 1e-5f);
    #pragma unroll
    for (int k = 0; k < 10; k++) {
        int c = lane + 32 * k;
        if (c < DD) p[c] = (v[k] - mu) * rsig * gamma[c] + beta[c];
    }
}

// LN both halves of merged row -> 640-wide fp16 hi/lo planes
__global__ void ln_merged_kernel(const float* __restrict__ merged,
                                 const float* __restrict__ g0, const float* __restrict__ b0,
                                 const float* __restrict__ g1, const float* __restrict__ b1) {
    int warp = (int)((blockIdx.x * (long)blockDim.x + threadIdx.x) >> 5);
    int lane = threadIdx.x & 31;
    if (warp >= NN) return;
    const float* prow = merged + (size_t)warp * (2 * DD);
    size_t orow = (size_t)warp * KPM;
    #pragma unroll
    for (int half = 0; half < 2; half++) {
        const float* p = prow + half * DD;
        const float* gamma = half ? g1 : g0;
        const float* beta  = half ? b1 : b0;
        float v[10];
        float sum = 0.f;
        #pragma unroll
        for (int k = 0; k < 10; k++) {
            int c = lane + 32 * k;
            v[k] = (c < DD) ? p[c] : 0.f;
            sum += v[k];
        }
        #pragma unroll
        for (int o = 16; o > 0; o >>= 1) sum += __shfl_xor_sync(0xFFFFFFFFu, sum, o);
        float mu = sum * (1.f / DD);
        float var = 0.f;
        #pragma unroll
        for (int k = 0; k < 10; k++) {
            int c = lane + 32 * k;
            float d = (c < DD) ? (v[k] - mu) : 0.f;
            var += d * d;
        }
        #pragma unroll
        for (int o = 16; o > 0; o >>= 1) var += __shfl_xor_sync(0xFFFFFFFFu, var, o);
        float rsig = rsqrtf(var * (1.f / DD) + 1e-5f);
        #pragma unroll
        for (int k = 0; k < 10; k++) {
            int c = lane + 32 * k;
            if (c < DD) {
                float w = (v[k] - mu) * rsig * gamma[c] + beta[c];
                fp16 h, l;
                split_fp16(w, h, l);
                g_mrg_h[orow + half * DD + c] = h;
                g_mrg_l[orow + half * DD + c] = l;
            }
        }
    }
    fp16 z = __float2half(0.f);
    g_mrg_h[orow + 600 + lane] = z;
    g_mrg_l[orow + 600 + lane] = z;
    if (lane < 8) {
        g_mrg_h[orow + 632 + lane] = z;
        g_mrg_l[orow + 632 + lane] = z;
    }
}

// ---------------- launch ----------------------------------------------------
extern "C" void kernel_launch(void* const* d_in, const int* in_sizes, int n_in,
                              void* d_out, int out_size) {
    const float* x    = (const float*)d_in[0];
    const int*   er   = (const int*)d_in[1];
    const int*   ec   = (const int*)d_in[2];
    const float* Wr   = (const float*)d_in[3];
    const float* br   = (const float*)d_in[4];
    const float* Wc   = (const float*)d_in[5];
    const float* bc   = (const float*)d_in[6];
    const float* Wrs  = (const float*)d_in[7];
    const float* brs  = (const float*)d_in[8];
    const float* g_rs = (const float*)d_in[9];
    const float* b_rs = (const float*)d_in[10];
    const float* Wcs  = (const float*)d_in[11];
    const float* bcs  = (const float*)d_in[12];
    const float* g_cs = (const float*)d_in[13];
    const float* b_cs = (const float*)d_in[14];
    const float* Wm   = (const float*)d_in[15];
    const float* bm   = (const float*)d_in[16];
    const float* g_m  = (const float*)d_in[17];
    const float* b_m  = (const float*)d_in[18];
    float* out = (float*)d_out;

    float *deg, *merged;
    cudaGetSymbolAddress((void**)&deg,    g_deg);
    cudaGetSymbolAddress((void**)&merged, g_merged);
    int *off_r, *off_c, *cur_r, *cur_c, *csr_r, *csr_c;
    cudaGetSymbolAddress((void**)&off_r, g_off_r);
    cudaGetSymbolAddress((void**)&off_c, g_off_c);
    cudaGetSymbolAddress((void**)&cur_r, g_cur_r);
    cudaGetSymbolAddress((void**)&cur_c, g_cur_c);
    cudaGetSymbolAddress((void**)&csr_r, g_csr_r);
    cudaGetSymbolAddress((void**)&csr_c, g_csr_c);

    fp16 *aggr_h, *aggr_l, *aggc_h, *aggc_l, *rowg_h, *rowg_l, *colg_h, *colg_l;
    fp16 *mrg_h, *mrg_l;
    fp16 *pWr, *pWc, *pWrs, *pWcs, *pWm;
    cudaGetSymbolAddress((void**)&aggr_h, g_aggr_h);
    cudaGetSymbolAddress((void**)&aggr_l, g_aggr_l);
    cudaGetSymbolAddress((void**)&aggc_h, g_aggc_h);
    cudaGetSymbolAddress((void**)&aggc_l, g_aggc_l);
    cudaGetSymbolAddress((void**)&rowg_h, g_rowg_h);
    cudaGetSymbolAddress((void**)&rowg_l, g_rowg_l);
    cudaGetSymbolAddress((void**)&colg_h, g_colg_h);
    cudaGetSymbolAddress((void**)&colg_l, g_colg_l);
    cudaGetSymbolAddress((void**)&mrg_h,  g_mrg_h);
    cudaGetSymbolAddress((void**)&mrg_l,  g_mrg_l);
    cudaGetSymbolAddress((void**)&pWr,  g_Wr);
    cudaGetSymbolAddress((void**)&pWc,  g_Wc);
    cudaGetSymbolAddress((void**)&pWrs, g_Wrs);
    cudaGetSymbolAddress((void**)&pWcs, g_Wcs);
    cudaGetSymbolAddress((void**)&pWm,  g_Wm);

    cudaFuncSetAttribute(gemm_tc2_kernel,
                         cudaFuncAttributeMaxDynamicSharedMemorySize, SMEM_GEMM);

    // graph preprocessing
    zero_ideg_kernel<<<(4 * NN + 255) / 256, 256>>>();
    degree_kernel<<<(NE + 255) / 256, 256>>>(er, ec);
    norm_kernel<<<(4 * NN + 255) / 256, 256>>>();
    dim3 sgrid(NSB, 2);
    scan1_kernel<<<sgrid, SB>>>();
    scan2_kernel<<<1, 256>>>(off_r, off_c);
    scan3_kernel<<<sgrid, SB>>>(off_r, cur_r, off_c, cur_c);
    fill_kernel<<<(NE + 255) / 256, 256>>>(er, cur_r, csr_r);
    fill_kernel<<<(NE + 255) / 256, 256>>>(ec, cur_c, csr_c);
    int ggrid = (NN * 32 + 255) / 256;
    gather_kernel<<<ggrid, 256>>>(csr_r, off_r, deg + 0 * NN, deg + 1 * NN, x, aggr_h, aggr_l);
    gather_kernel<<<ggrid, 256>>>(csr_c, off_c, deg + 2 * NN, deg + 3 * NN, x, aggc_h, aggc_l);
    tail_zero_kernel<<<((MP - NN) * KPM + 255) / 256, 256>>>();

    // weight converts (single fp16 plane)
    int wgrid = (KP1 * NP + 255) / 256;
    w_convert_kernel<<<wgrid, 256>>>(Wr,  DD, DD, KP1, pWr);
    w_convert_kernel<<<wgrid, 256>>>(Wc,  DD, DD, KP1, pWc);
    w_convert_kernel<<<wgrid, 256>>>(Wrs, DD, DD, KP1, pWrs);
    w_convert_kernel<<<wgrid, 256>>>(Wcs, DD, DD, KP1, pWcs);
    w_convert_kernel<<<(KPM * NP + 255) / 256, 256>>>(Wm, 2 * DD, DD, KPM, pWm);

    dim3 gg(NP / GBN, MP / GBM);   // (5, 782)
    const int nK1 = KP1 / GBK;     // 5
    const int nKm = KPM / GBK;     // 10

    // GraphConv GEMMs -> relu -> fp16 hi/lo planes
    gemm_tc2_kernel<<<gg, 256, SMEM_GEMM>>>(aggr_h, aggr_l, KP1, pWr, br,
        NN, DD, nK1, 1, 1, nullptr, 0, rowg_h, rowg_l, KP1);
    gemm_tc2_kernel<<<gg, 256, SMEM_GEMM>>>(aggc_h, aggc_l, KP1, pWc, bc,
        NN, DD, nK1, 1, 1, nullptr, 0, colg_h, colg_l, KP1);

    // support GEMMs -> fp32 merged halves
    gemm_tc2_kernel<<<gg, 256, SMEM_GEMM>>>(rowg_h, rowg_l, KP1, pWrs, brs,
        NN, DD, nK1, 0, 0, merged, 2 * DD, nullptr, nullptr, 0);
    gemm_tc2_kernel<<<gg, 256, SMEM_GEMM>>>(colg_h, colg_l, KP1, pWcs, bcs,
        NN, DD, nK1, 0, 0, merged + DD, 2 * DD, nullptr, nullptr, 0);

    // LN both halves -> 640-wide mrg planes
    int lngrid = (NN + 7) / 8;
    ln_merged_kernel<<<lngrid, 256>>>(merged, g_rs, b_rs, g_cs, b_cs);

    // merge GEMM (K=640) -> fp32 out, then final LN
    gemm_tc2_kernel<<<gg, 256, SMEM_GEMM>>>(mrg_h, mrg_l, KPM, pWm, bm,
        NN, DD, nKm, 0, 0, out, DD, nullptr, nullptr, 0);
    ln_kernel<<<lngrid, 256>>>(out, DD, g_m, b_m, NN);
}

// round 10
// speedup vs baseline: 2.9887x; 1.3121x over previous
#include <cuda_runtime.h>
#include <cuda_fp16.h>
#include <cstddef>
#include <cstdint>

#define NN 100000
#define NE 1000000
#define DD 300
#define MP 100096      // NN padded to 128
#define KP1 320        // K=300 padded
#define NP  320        // N=300 padded
#define KPM 640        // merge K=600 padded

typedef __half fp16;
typedef __half2 fp162;

// ---------------- scratch (device globals; no allocation allowed) ----------
__device__ int   g_ideg[4 * NN];
__device__ float g_deg[4 * NN];
__device__ int   g_off_r[NN + 1], g_off_c[NN + 1];
__device__ int   g_cur_r[NN],     g_cur_c[NN];
__device__ int   g_csr_r[NE],     g_csr_c[NE];
__device__ __align__(16) float g_merged[(size_t)NN * 2 * DD];

#define SB 1024
#define NSB ((NN + SB - 1) / SB)   // 98
__device__ int g_bsum[2][NSB];
__device__ int g_boff[2][NSB];

// fp16 operand planes (padded, M x K row-major)
__device__ __align__(16) fp16 g_aggr[(size_t)MP * KP1];
__device__ __align__(16) fp16 g_aggc[(size_t)MP * KP1];
__device__ __align__(16) fp16 g_rowg[(size_t)MP * KP1];
__device__ __align__(16) fp16 g_colg[(size_t)MP * KP1];
__device__ __align__(16) fp16 g_mrg[(size_t)MP * KPM];
// weight planes (single fp16): K x N row-major
__device__ __align__(16) fp16 g_Wr[KP1 * NP];
__device__ __align__(16) fp16 g_Wc[KP1 * NP];
__device__ __align__(16) fp16 g_Wrs[KP1 * NP];
__device__ __align__(16) fp16 g_Wcs[KP1 * NP];
__device__ __align__(16) fp16 g_Wm[KPM * NP];

// ---------------- helpers ----------------------------------------------------
__device__ __forceinline__ uint32_t pack2(fp16 a, fp16 b) {
    fp162 t = __halves2half2(a, b);
    return *(uint32_t*)&t;
}
#define SWZ(x) ((x) ^ (((x) >> 3) & 0x70))
__device__ __forceinline__ void cp16(uint32_t dst, const void* src) {
    asm volatile("cp.async.cg.shared.global [%0], [%1], 16;" :: "r"(dst), "l"(src));
}
__device__ __forceinline__ void ldsm_x4(uint32_t& r0, uint32_t& r1, uint32_t& r2, uint32_t& r3,
                                        uint32_t addr) {
    asm volatile("ldmatrix.sync.aligned.m8n8.x4.shared.b16 {%0,%1,%2,%3}, [%4];"
                 : "=r"(r0), "=r"(r1), "=r"(r2), "=r"(r3) : "r"(addr));
}
__device__ __forceinline__ void ldsm_x4_t(uint32_t& r0, uint32_t& r1, uint32_t& r2, uint32_t& r3,
                                          uint32_t addr) {
    asm volatile("ldmatrix.sync.aligned.m8n8.x4.trans.shared.b16 {%0,%1,%2,%3}, [%4];"
                 : "=r"(r0), "=r"(r1), "=r"(r2), "=r"(r3) : "r"(addr));
}
__device__ __forceinline__ void mma_fp16(float* c, const uint32_t* a, const uint32_t* b) {
    asm volatile("mma.sync.aligned.m16n8k16.row.col.f32.f16.f16.f32 "
                 "{%0,%1,%2,%3}, {%4,%5,%6,%7}, {%8,%9}, {%0,%1,%2,%3};"
                 : "+f"(c[0]), "+f"(c[1]), "+f"(c[2]), "+f"(c[3])
                 : "r"(a[0]), "r"(a[1]), "r"(a[2]), "r"(a[3]), "r"(b[0]), "r"(b[1]));
}

// ---------------- graph preprocessing ----------------------------------------
__global__ void zero_ideg_kernel() {
    int i = blockIdx.x * blockDim.x + threadIdx.x;
    if (i < 4 * NN) g_ideg[i] = 0;
}

__global__ void degree_kernel(const int* __restrict__ er, const int* __restrict__ ec) {
    int i = blockIdx.x * blockDim.x + threadIdx.x;
    if (i < NE) {
        atomicAdd(&g_ideg[0 * NN + er[i]],      1);
        atomicAdd(&g_ideg[1 * NN + er[NE + i]], 1);
        atomicAdd(&g_ideg[2 * NN + ec[i]],      1);
        atomicAdd(&g_ideg[3 * NN + ec[NE + i]], 1);
    }
}

__global__ void norm_kernel() {
    int i = blockIdx.x * blockDim.x + threadIdx.x;
    if (i < 4 * NN) {
        int d = g_ideg[i];
        g_deg[i] = (d > 0) ? rsqrtf((float)d) : 0.f;
    }
}

__global__ __launch_bounds__(SB) void scan1_kernel() {
    int gsel = blockIdx.y;
    const int* deg = g_ideg + (gsel ? 3 : 1) * NN;
    int i = blockIdx.x * SB + threadIdx.x;
    int v = (i < NN) ? deg[i] : 0;
    __shared__ int ws[32];
    #pragma unroll
    for (int o = 16; o > 0; o >>= 1) v += __shfl_xor_sync(0xFFFFFFFFu, v, o);
    if ((threadIdx.x & 31) == 0) ws[threadIdx.x >> 5] = v;
    __syncthreads();
    if (threadIdx.x < 32) {
        int s = (threadIdx.x < SB / 32) ? ws[threadIdx.x] : 0;
        #pragma unroll
        for (int o = 16; o > 0; o >>= 1) s += __shfl_xor_sync(0xFFFFFFFFu, s, o);
        if (threadIdx.x == 0) g_bsum[gsel][blockIdx.x] = s;
    }
}

__global__ __launch_bounds__(256) void scan2_kernel(int* __restrict__ off_r,
                                                    int* __restrict__ off_c) {
    __shared__ int ss[2][128];
    int t = threadIdx.x;
    int h = t >> 7;
    int j = t & 127;
    int v = (j < NSB) ? g_bsum[h][j] : 0;
    ss[h][j] = v;
    __syncthreads();
    #pragma unroll
    for (int d = 1; d < 128; d <<= 1) {
        int u = (j >= d) ? ss[h][j - d] : 0;
        __syncthreads();
        ss[h][j] += u;
        __syncthreads();
    }
    if (j < NSB) g_boff[h][j] = ss[h][j] - v;
    if (t == 0) { off_r[NN] = NE; off_c[NN] = NE; }
}

__global__ __launch_bounds__(SB) void scan3_kernel(int* __restrict__ off_r,
                                                   int* __restrict__ cur_r,
                                                   int* __restrict__ off_c,
                                                   int* __restrict__ cur_c) {
    int gsel = blockIdx.y;
    const int* deg = g_ideg + (gsel ? 3 : 1) * NN;
    int* off = gsel ? off_c : off_r;
    int* cur = gsel ? cur_c : cur_r;
    __shared__ int ss[SB];
    int i = blockIdx.x * SB + threadIdx.x;
    int v = (i < NN) ? deg[i] : 0;
    ss[threadIdx.x] = v;
    __syncthreads();
    #pragma unroll
    for (int d = 1; d < SB; d <<= 1) {
        int u = (threadIdx.x >= d) ? ss[threadIdx.x - d] : 0;
        __syncthreads();
        ss[threadIdx.x] += u;
        __syncthreads();
    }
    if (i < NN) {
        int excl = ss[threadIdx.x] - v + g_boff[gsel][blockIdx.x];
        off[i] = excl;
        cur[i] = excl;
    }
}

__global__ void fill_kernel(const int* __restrict__ edges,
                            int* __restrict__ cur, int* __restrict__ csr) {
    int i = blockIdx.x * blockDim.x + threadIdx.x;
    if (i < NE) {
        int s = edges[i];
        int d = edges[NE + i];
        int pos = atomicAdd(&cur[d], 1);
        csr[pos] = s;
    }
}

// one warp per node, float4 loads; fuses dst-norm + fp16 round
__global__ __launch_bounds__(256) void gather_kernel(
    const int* __restrict__ csr, const int* __restrict__ off,
    const float* __restrict__ nsrc, const float* __restrict__ ndst,
    const float* __restrict__ x,
    fp16* __restrict__ Ah) {
    int warp = (int)((blockIdx.x * (long)blockDim.x + threadIdx.x) >> 5);
    int lane = threadIdx.x & 31;
    if (warp >= NN) return;
    int o0 = off[warp], o1 = off[warp + 1];
    float4 a0 = make_float4(0.f, 0.f, 0.f, 0.f);
    float4 a1 = a0, a2 = a0;
    for (int j = o0; j < o1; j++) {
        int s = csr[j];
        float ns = nsrc[s];
        const float4* xr = (const float4*)(x + (size_t)s * DD);
        float4 v = xr[lane];
        a0.x += v.x * ns; a0.y += v.y * ns; a0.z += v.z * ns; a0.w += v.w * ns;
        v = xr[32 + lane];
        a1.x += v.x * ns; a1.y += v.y * ns; a1.z += v.z * ns; a1.w += v.w * ns;
        if (lane < 11) {
            v = xr[64 + lane];
            a2.x += v.x * ns; a2.y += v.y * ns; a2.z += v.z * ns; a2.w += v.w * ns;
        }
    }
    float nd = ndst[warp];
    size_t orow = (size_t)warp * KP1;
    auto store4 = [&](float4 a, int f4i) {
        uint2 hh = make_uint2(
            pack2(__float2half(a.x * nd), __float2half(a.y * nd)),
            pack2(__float2half(a.z * nd), __float2half(a.w * nd)));
        *(uint2*)&Ah[orow + f4i * 4] = hh;
    };
    store4(a0, lane);
    store4(a1, 32 + lane);
    if (lane < 11) store4(a2, 64 + lane);
    if (lane < 20) Ah[orow + 300 + lane] = __float2half(0.f);
}

// zero tail rows [NN, MP) of agg + mrg planes
__global__ void tail_zero_kernel() {
    int i = blockIdx.x * blockDim.x + threadIdx.x;
    const int nAgg = (MP - NN) * KP1;
    const int nMrg = (MP - NN) * KPM;
    fp16 z = __float2half(0.f);
    if (i < nAgg) {
        size_t o = (size_t)NN * KP1 + i;
        g_aggr[o] = z;
        g_aggc[o] = z;
    }
    if (i < nMrg) g_mrg[(size_t)NN * KPM + i] = z;
}

// weight (K x Ncols fp32) -> fp16 plane (KPp x NP), zero padded
__global__ void w_convert_kernel(const float* __restrict__ W, int K, int Ncols, int KPp,
                                 fp16* __restrict__ Wh) {
    int idx = blockIdx.x * blockDim.x + threadIdx.x;
    if (idx >= KPp * NP) return;
    int k = idx / NP;
    int n = idx - k * NP;
    float v = (k < K && n < Ncols) ? W[(size_t)k * Ncols + n] : 0.f;
    Wh[idx] = __float2half(v);
}

// ====== Tensor-core GEMM: fp16 single-pass, SW128, GBK=64, 2-stage ==========
#define GBM 128
#define GBN 64
#define GBK 64
#define A_PL 16384u                 // 128 rows x 128B
#define B_PL 8192u                  // 64 rows x 128B
#define STG (A_PL + B_PL)           // 24576
#define SMEM_GEMM (2 * STG)         // 49152

__global__ __launch_bounds__(256) void gemm_tc2_kernel(
    const fp16* __restrict__ Ap, int lda,
    const fp16* __restrict__ Bp,
    const float* __restrict__ bias,
    int M, int Ncols, int nK, int mode, int relu,
    float* __restrict__ Cf, int ldc,
    fp16* __restrict__ Ch, int ldcp)
{
    extern __shared__ __align__(128) char smem[];
    const uint32_t sb = (uint32_t)__cvta_generic_to_shared(smem);

    const int t = threadIdx.x;
    const int wid = t >> 5;
    const int lane = t & 31;
    const int warp_m = wid >> 1;
    const int warp_n = wid & 1;
    const int m0 = blockIdx.y * GBM;
    const int n0 = blockIdx.x * GBN;

    float acc[2][4][4];
    #pragma unroll
    for (int mi = 0; mi < 2; mi++)
        #pragma unroll
        for (int ni = 0; ni < 4; ni++)
            #pragma unroll
            for (int j = 0; j < 4; j++) acc[mi][ni][j] = 0.f;

    auto load_stage = [&](int stage, int k0) {
        const uint32_t base = sb + (uint32_t)stage * STG;
        const uint32_t aA = base;
        const uint32_t aB = base + A_PL;
        #pragma unroll
        for (int i = 0; i < 4; i++) {
            int idx = i * 256 + t;
            int r = idx >> 3, c = idx & 7;
            uint32_t d = SWZ((uint32_t)(r * 128 + c * 16));
            cp16(aA + d, Ap + (size_t)(m0 + r) * lda + k0 + c * 8);
        }
        #pragma unroll
        for (int i = 0; i < 2; i++) {
            int idx = i * 256 + t;
            int r = idx >> 3, c = idx & 7;
            uint32_t d = SWZ((uint32_t)(r * 128 + c * 16));
            cp16(aB + d, Bp + (size_t)(k0 + r) * NP + n0 + c * 8);
        }
        asm volatile("cp.async.commit_group;");
    };

    load_stage(0, 0);

    const int lrow = lane & 15;
    const int lhi = lane >> 4;

    for (int kt = 0; kt < nK; kt++) {
        if (kt + 1 < nK) {
            load_stage((kt + 1) & 1, (kt + 1) * GBK);
            asm volatile("cp.async.wait_group 1;");
        } else {
            asm volatile("cp.async.wait_group 0;");
        }
        __syncthreads();

        const uint32_t base = sb + (uint32_t)(kt & 1) * STG;
        const uint32_t aA = base;
        const uint32_t aB = base + A_PL;

        #pragma unroll
        for (int ks = 0; ks < 4; ks++) {
            uint32_t ah[2][4];
            #pragma unroll
            for (int mi = 0; mi < 2; mi++) {
                int row = warp_m * 32 + mi * 16 + lrow;
                uint32_t off = SWZ((uint32_t)(row * 128 + ks * 32 + lhi * 16));
                ldsm_x4(ah[mi][0], ah[mi][1], ah[mi][2], ah[mi][3], aA + off);
            }
            uint32_t bh[4][2];
            #pragma unroll
            for (int nj = 0; nj < 2; nj++) {
                int krow = ks * 16 + lrow;
                uint32_t off = SWZ((uint32_t)(krow * 128 + warp_n * 64 + nj * 32 + lhi * 16));
                uint32_t r0, r1, r2, r3;
                ldsm_x4_t(r0, r1, r2, r3, aB + off);
                bh[nj * 2 + 0][0] = r0; bh[nj * 2 + 0][1] = r1;
                bh[nj * 2 + 1][0] = r2; bh[nj * 2 + 1][1] = r3;
            }
            #pragma unroll
            for (int mi = 0; mi < 2; mi++)
                #pragma unroll
                for (int ni = 0; ni < 4; ni++)
                    mma_fp16(acc[mi][ni], ah[mi], bh[ni]);
        }
        __syncthreads();
    }

    // ---- epilogue ----
    const int g = lane >> 2;
    const int tig = lane & 3;
    #pragma unroll
    for (int mi = 0; mi < 2; mi++) {
        #pragma unroll
        for (int ni = 0; ni < 4; ni++) {
            int col = n0 + warp_n * 32 + ni * 8 + tig * 2;
            float bx = 0.f, by = 0.f;
            if (bias != nullptr && col < Ncols) {
                bx = bias[col];
                if (col + 1 < Ncols) by = bias[col + 1];
            }
            #pragma unroll
            for (int rr = 0; rr < 2; rr++) {
                int row = m0 + warp_m * 32 + mi * 16 + g + rr * 8;
                float vx = acc[mi][ni][rr * 2 + 0] + bx;
                float vy = acc[mi][ni][rr * 2 + 1] + by;
                if (relu) { vx = fmaxf(vx, 0.f); vy = fmaxf(vy, 0.f); }
                if (mode == 0) {
                    if (row < M && col < Ncols)
                        *(float2*)(Cf + (size_t)row * ldc + col) = make_float2(vx, vy);
                } else {
                    bool ok = (row < M) && (col < Ncols);
                    if (!ok) { vx = 0.f; vy = 0.f; }
                    if (!(ok && col + 1 < Ncols)) vy = 0.f;
                    *(uint32_t*)&Ch[(size_t)row * ldcp + col] =
                        pack2(__float2half(vx), __float2half(vy));
                }
            }
        }
    }
}

// ---------------- LayerNorm (fp32, in place) --------------------------------
__global__ void ln_kernel(float* __restrict__ X, int ld,
                          const float* __restrict__ gamma,
                          const float* __restrict__ beta, int M) {
    int warp = (int)((blockIdx.x * (long)blockDim.x + threadIdx.x) >> 5);
    int lane = threadIdx.x & 31;
    if (warp >= M) return;
    float* p = X + (size_t)warp * ld;
    float v[10];
    float sum = 0.f;
    #pragma unroll
    for (int k = 0; k < 10; k++) {
        int c = lane + 32 * k;
        v[k] = (c < DD) ? p[c] : 0.f;
        sum += v[k];
    }
    #pragma unroll
    for (int o = 16; o > 0; o >>= 1) sum += __shfl_xor_sync(0xFFFFFFFFu, sum, o);
    float mu = sum * (1.f / DD);
    float var = 0.f;
    #pragma unroll
    for (int k = 0; k < 10; k++) {
        int c = lane + 32 * k;
        float d = (c < DD) ? (v[k] - mu) : 0.f;
        var += d * d;
    }
    #pragma unroll
    for (int o = 16; o > 0; o >>= 1) var += __shfl_xor_sync(0xFFFFFFFFu, var, o);
    float rsig = rsqrtf(var * (1.f / DD) + 1e-5f);
    #pragma unroll
    for (int k = 0; k < 10; k++) {
        int c = lane + 32 * k;
        if (c < DD) p[c] = (v[k] - mu) * rsig * gamma[c] + beta[c];
    }
}

// LN both halves of merged row -> 640-wide fp16 plane
__global__ void ln_merged_kernel(const float* __restrict__ merged,
                                 const float* __restrict__ g0, const float* __restrict__ b0,
                                 const float* __restrict__ g1, const float* __restrict__ b1) {
    int warp = (int)((blockIdx.x * (long)blockDim.x + threadIdx.x) >> 5);
    int lane = threadIdx.x & 31;
    if (warp >= NN) return;
    const float* prow = merged + (size_t)warp * (2 * DD);
    size_t orow = (size_t)warp * KPM;
    #pragma unroll
    for (int half = 0; half < 2; half++) {
        const float* p = prow + half * DD;
        const float* gamma = half ? g1 : g0;
        const float* beta  = half ? b1 : b0;
        float v[10];
        float sum = 0.f;
        #pragma unroll
        for (int k = 0; k < 10; k++) {
            int c = lane + 32 * k;
            v[k] = (c < DD) ? p[c] : 0.f;
            sum += v[k];
        }
        #pragma unroll
        for (int o = 16; o > 0; o >>= 1) sum += __shfl_xor_sync(0xFFFFFFFFu, sum, o);
        float mu = sum * (1.f / DD);
        float var = 0.f;
        #pragma unroll
        for (int k = 0; k < 10; k++) {
            int c = lane + 32 * k;
            float d = (c < DD) ? (v[k] - mu) : 0.f;
            var += d * d;
        }
        #pragma unroll
        for (int o = 16; o > 0; o >>= 1) var += __shfl_xor_sync(0xFFFFFFFFu, var, o);
        float rsig = rsqrtf(var * (1.f / DD) + 1e-5f);
        #pragma unroll
        for (int k = 0; k < 10; k++) {
            int c = lane + 32 * k;
            if (c < DD) {
                float w = (v[k] - mu) * rsig * gamma[c] + beta[c];
                g_mrg[orow + half * DD + c] = __float2half(w);
            }
        }
    }
    fp16 z = __float2half(0.f);
    g_mrg[orow + 600 + lane] = z;
    if (lane < 8) g_mrg[orow + 632 + lane] = z;
}

// ---------------- launch ----------------------------------------------------
extern "C" void kernel_launch(void* const* d_in, const int* in_sizes, int n_in,
                              void* d_out, int out_size) {
    const float* x    = (const float*)d_in[0];
    const int*   er   = (const int*)d_in[1];
    const int*   ec   = (const int*)d_in[2];
    const float* Wr   = (const float*)d_in[3];
    const float* br   = (const float*)d_in[4];
    const float* Wc   = (const float*)d_in[5];
    const float* bc   = (const float*)d_in[6];
    const float* Wrs  = (const float*)d_in[7];
    const float* brs  = (const float*)d_in[8];
    const float* g_rs = (const float*)d_in[9];
    const float* b_rs = (const float*)d_in[10];
    const float* Wcs  = (const float*)d_in[11];
    const float* bcs  = (const float*)d_in[12];
    const float* g_cs = (const float*)d_in[13];
    const float* b_cs = (const float*)d_in[14];
    const float* Wm   = (const float*)d_in[15];
    const float* bm   = (const float*)d_in[16];
    const float* g_m  = (const float*)d_in[17];
    const float* b_m  = (const float*)d_in[18];
    float* out = (float*)d_out;

    float *deg, *merged;
    cudaGetSymbolAddress((void**)&deg,    g_deg);
    cudaGetSymbolAddress((void**)&merged, g_merged);
    int *off_r, *off_c, *cur_r, *cur_c, *csr_r, *csr_c;
    cudaGetSymbolAddress((void**)&off_r, g_off_r);
    cudaGetSymbolAddress((void**)&off_c, g_off_c);
    cudaGetSymbolAddress((void**)&cur_r, g_cur_r);
    cudaGetSymbolAddress((void**)&cur_c, g_cur_c);
    cudaGetSymbolAddress((void**)&csr_r, g_csr_r);
    cudaGetSymbolAddress((void**)&csr_c, g_csr_c);

    fp16 *aggr, *aggc, *rowg, *colg, *mrg;
    fp16 *pWr, *pWc, *pWrs, *pWcs, *pWm;
    cudaGetSymbolAddress((void**)&aggr, g_aggr);
    cudaGetSymbolAddress((void**)&aggc, g_aggc);
    cudaGetSymbolAddress((void**)&rowg, g_rowg);
    cudaGetSymbolAddress((void**)&colg, g_colg);
    cudaGetSymbolAddress((void**)&mrg,  g_mrg);
    cudaGetSymbolAddress((void**)&pWr,  g_Wr);
    cudaGetSymbolAddress((void**)&pWc,  g_Wc);
    cudaGetSymbolAddress((void**)&pWrs, g_Wrs);
    cudaGetSymbolAddress((void**)&pWcs, g_Wcs);
    cudaGetSymbolAddress((void**)&pWm,  g_Wm);

    cudaFuncSetAttribute(gemm_tc2_kernel,
                         cudaFuncAttributeMaxDynamicSharedMemorySize, SMEM_GEMM);

    // graph preprocessing
    zero_ideg_kernel<<<(4 * NN + 255) / 256, 256>>>();
    degree_kernel<<<(NE + 255) / 256, 256>>>(er, ec);
    norm_kernel<<<(4 * NN + 255) / 256, 256>>>();
    dim3 sgrid(NSB, 2);
    scan1_kernel<<<sgrid, SB>>>();
    scan2_kernel<<<1, 256>>>(off_r, off_c);
    scan3_kernel<<<sgrid, SB>>>(off_r, cur_r, off_c, cur_c);
    fill_kernel<<<(NE + 255) / 256, 256>>>(er, cur_r, csr_r);
    fill_kernel<<<(NE + 255) / 256, 256>>>(ec, cur_c, csr_c);
    int ggrid = (NN * 32 + 255) / 256;
    gather_kernel<<<ggrid, 256>>>(csr_r, off_r, deg + 0 * NN, deg + 1 * NN, x, aggr);
    gather_kernel<<<ggrid, 256>>>(csr_c, off_c, deg + 2 * NN, deg + 3 * NN, x, aggc);
    tail_zero_kernel<<<((MP - NN) * KPM + 255) / 256, 256>>>();

    // weight converts
    int wgrid = (KP1 * NP + 255) / 256;
    w_convert_kernel<<<wgrid, 256>>>(Wr,  DD, DD, KP1, pWr);
    w_convert_kernel<<<wgrid, 256>>>(Wc,  DD, DD, KP1, pWc);
    w_convert_kernel<<<wgrid, 256>>>(Wrs, DD, DD, KP1, pWrs);
    w_convert_kernel<<<wgrid, 256>>>(Wcs, DD, DD, KP1, pWcs);
    w_convert_kernel<<<(KPM * NP + 255) / 256, 256>>>(Wm, 2 * DD, DD, KPM, pWm);

    dim3 gg(NP / GBN, MP / GBM);   // (5, 782)
    const int nK1 = KP1 / GBK;     // 5
    const int nKm = KPM / GBK;     // 10

    // GraphConv GEMMs -> relu -> fp16 planes
    gemm_tc2_kernel<<<gg, 256, SMEM_GEMM>>>(aggr, KP1, pWr, br,
        NN, DD, nK1, 1, 1, nullptr, 0, rowg, KP1);
    gemm_tc2_kernel<<<gg, 256, SMEM_GEMM>>>(aggc, KP1, pWc, bc,
        NN, DD, nK1, 1, 1, nullptr, 0, colg, KP1);

    // support GEMMs -> fp32 merged halves
    gemm_tc2_kernel<<<gg, 256, SMEM_GEMM>>>(rowg, KP1, pWrs, brs,
        NN, DD, nK1, 0, 0, merged, 2 * DD, nullptr, 0);
    gemm_tc2_kernel<<<gg, 256, SMEM_GEMM>>>(colg, KP1, pWcs, bcs,
        NN, DD, nK1, 0, 0, merged + DD, 2 * DD, nullptr, 0);

    // LN both halves -> 640-wide mrg plane
    int lngrid = (NN + 7) / 8;
    ln_merged_kernel<<<lngrid, 256>>>(merged, g_rs, b_rs, g_cs, b_cs);

    // merge GEMM (K=640) -> fp32 out, then final LN
    gemm_tc2_kernel<<<gg, 256, SMEM_GEMM>>>(mrg, KPM, pWm, bm,
        NN, DD, nKm, 0, 0, out, DD, nullptr, 0);
    ln_kernel<<<lngrid, 256>>>(out, DD, g_m, b_m, NN);
}

// round 11
// speedup vs baseline: 3.2747x; 1.0957x over previous
#include <cuda_runtime.h>
#include <cuda_fp16.h>
#include <cstddef>
#include <cstdint>

#define NN 100000
#define NE 1000000
#define DD 300
#define MP 100096      // NN padded to 128
#define KP1 320        // K=300 padded
#define NP  320        // N=300 padded
#define KPM 640        // merge K=600 padded

typedef __half fp16;
typedef __half2 fp162;

// ---------------- scratch (device globals; no allocation allowed) ----------
__device__ int   g_ideg[4 * NN];
__device__ float g_deg[4 * NN];
__device__ int   g_off_r[NN + 1], g_off_c[NN + 1];
__device__ int   g_cur_r[NN],     g_cur_c[NN];
__device__ int   g_csr_r[NE],     g_csr_c[NE];

#define SB 1024
#define NSB ((NN + SB - 1) / SB)   // 98
__device__ int g_bsum[2][NSB];
__device__ int g_boff[2][NSB];

// fp16 feature table (NN x DD)
__device__ __align__(16) fp16 g_xh[(size_t)NN * DD];
// fp16 operand planes (padded, M x K row-major)
__device__ __align__(16) fp16 g_aggr[(size_t)MP * KP1];
__device__ __align__(16) fp16 g_aggc[(size_t)MP * KP1];
__device__ __align__(16) fp16 g_rowg[(size_t)MP * KP1];
__device__ __align__(16) fp16 g_colg[(size_t)MP * KP1];
__device__ __align__(16) fp16 g_mrg[(size_t)MP * KPM];
// weight planes (single fp16): K x N row-major
__device__ __align__(16) fp16 g_Wr[KP1 * NP];
__device__ __align__(16) fp16 g_Wc[KP1 * NP];
__device__ __align__(16) fp16 g_Wrs[KP1 * NP];
__device__ __align__(16) fp16 g_Wcs[KP1 * NP];
__device__ __align__(16) fp16 g_Wm[KPM * NP];

// ---------------- helpers ----------------------------------------------------
__device__ __forceinline__ uint32_t pack2(fp16 a, fp16 b) {
    fp162 t = __halves2half2(a, b);
    return *(uint32_t*)&t;
}
#define SWZ(x) ((x) ^ (((x) >> 3) & 0x70))
__device__ __forceinline__ void cp16(uint32_t dst, const void* src) {
    asm volatile("cp.async.cg.shared.global [%0], [%1], 16;" :: "r"(dst), "l"(src));
}
__device__ __forceinline__ void ldsm_x4(uint32_t& r0, uint32_t& r1, uint32_t& r2, uint32_t& r3,
                                        uint32_t addr) {
    asm volatile("ldmatrix.sync.aligned.m8n8.x4.shared.b16 {%0,%1,%2,%3}, [%4];"
                 : "=r"(r0), "=r"(r1), "=r"(r2), "=r"(r3) : "r"(addr));
}
__device__ __forceinline__ void ldsm_x4_t(uint32_t& r0, uint32_t& r1, uint32_t& r2, uint32_t& r3,
                                          uint32_t addr) {
    asm volatile("ldmatrix.sync.aligned.m8n8.x4.trans.shared.b16 {%0,%1,%2,%3}, [%4];"
                 : "=r"(r0), "=r"(r1), "=r"(r2), "=r"(r3) : "r"(addr));
}
__device__ __forceinline__ void mma_fp16(float* c, const uint32_t* a, const uint32_t* b) {
    asm volatile("mma.sync.aligned.m16n8k16.row.col.f32.f16.f16.f32 "
                 "{%0,%1,%2,%3}, {%4,%5,%6,%7}, {%8,%9}, {%0,%1,%2,%3};"
                 : "+f"(c[0]), "+f"(c[1]), "+f"(c[2]), "+f"(c[3])
                 : "r"(a[0]), "r"(a[1]), "r"(a[2]), "r"(a[3]), "r"(b[0]), "r"(b[1]));
}

// ---------------- graph preprocessing ----------------------------------------
__global__ void zero_ideg_kernel() {
    int i = blockIdx.x * blockDim.x + threadIdx.x;
    if (i < 4 * NN) g_ideg[i] = 0;
}

__global__ void degree_kernel(const int* __restrict__ er, const int* __restrict__ ec) {
    int i = blockIdx.x * blockDim.x + threadIdx.x;
    if (i < NE) {
        atomicAdd(&g_ideg[0 * NN + er[i]],      1);
        atomicAdd(&g_ideg[1 * NN + er[NE + i]], 1);
        atomicAdd(&g_ideg[2 * NN + ec[i]],      1);
        atomicAdd(&g_ideg[3 * NN + ec[NE + i]], 1);
    }
}

__global__ void norm_kernel() {
    int i = blockIdx.x * blockDim.x + threadIdx.x;
    if (i < 4 * NN) {
        int d = g_ideg[i];
        g_deg[i] = (d > 0) ? rsqrtf((float)d) : 0.f;
    }
}

// x fp32 -> fp16 table
__global__ void x_convert_kernel(const float2* __restrict__ x) {
    long i = (long)blockIdx.x * blockDim.x + threadIdx.x;
    if (i < (long)NN * DD / 2) {
        float2 v = x[i];
        *(uint32_t*)&g_xh[i * 2] = pack2(__float2half(v.x), __float2half(v.y));
    }
}

__global__ __launch_bounds__(SB) void scan1_kernel() {
    int gsel = blockIdx.y;
    const int* deg = g_ideg + (gsel ? 3 : 1) * NN;
    int i = blockIdx.x * SB + threadIdx.x;
    int v = (i < NN) ? deg[i] : 0;
    __shared__ int ws[32];
    #pragma unroll
    for (int o = 16; o > 0; o >>= 1) v += __shfl_xor_sync(0xFFFFFFFFu, v, o);
    if ((threadIdx.x & 31) == 0) ws[threadIdx.x >> 5] = v;
    __syncthreads();
    if (threadIdx.x < 32) {
        int s = (threadIdx.x < SB / 32) ? ws[threadIdx.x] : 0;
        #pragma unroll
        for (int o = 16; o > 0; o >>= 1) s += __shfl_xor_sync(0xFFFFFFFFu, s, o);
        if (threadIdx.x == 0) g_bsum[gsel][blockIdx.x] = s;
    }
}

__global__ __launch_bounds__(256) void scan2_kernel(int* __restrict__ off_r,
                                                    int* __restrict__ off_c) {
    __shared__ int ss[2][128];
    int t = threadIdx.x;
    int h = t >> 7;
    int j = t & 127;
    int v = (j < NSB) ? g_bsum[h][j] : 0;
    ss[h][j] = v;
    __syncthreads();
    #pragma unroll
    for (int d = 1; d < 128; d <<= 1) {
        int u = (j >= d) ? ss[h][j - d] : 0;
        __syncthreads();
        ss[h][j] += u;
        __syncthreads();
    }
    if (j < NSB) g_boff[h][j] = ss[h][j] - v;
    if (t == 0) { off_r[NN] = NE; off_c[NN] = NE; }
}

__global__ __launch_bounds__(SB) void scan3_kernel(int* __restrict__ off_r,
                                                   int* __restrict__ cur_r,
                                                   int* __restrict__ off_c,
                                                   int* __restrict__ cur_c) {
    int gsel = blockIdx.y;
    const int* deg = g_ideg + (gsel ? 3 : 1) * NN;
    int* off = gsel ? off_c : off_r;
    int* cur = gsel ? cur_c : cur_r;
    __shared__ int ss[SB];
    int i = blockIdx.x * SB + threadIdx.x;
    int v = (i < NN) ? deg[i] : 0;
    ss[threadIdx.x] = v;
    __syncthreads();
    #pragma unroll
    for (int d = 1; d < SB; d <<= 1) {
        int u = (threadIdx.x >= d) ? ss[threadIdx.x - d] : 0;
        __syncthreads();
        ss[threadIdx.x] += u;
        __syncthreads();
    }
    if (i < NN) {
        int excl = ss[threadIdx.x] - v + g_boff[gsel][blockIdx.x];
        off[i] = excl;
        cur[i] = excl;
    }
}

__global__ void fill_kernel(const int* __restrict__ edges,
                            int* __restrict__ cur, int* __restrict__ csr) {
    int i = blockIdx.x * blockDim.x + threadIdx.x;
    if (i < NE) {
        int s = edges[i];
        int d = edges[NE + i];
        int pos = atomicAdd(&cur[d], 1);
        csr[pos] = s;
    }
}

// one warp per node; fp16 x reads (uint2 = 4 halves), fp32 accumulate
__global__ __launch_bounds__(256) void gather_kernel(
    const int* __restrict__ csr, const int* __restrict__ off,
    const float* __restrict__ nsrc, const float* __restrict__ ndst,
    fp16* __restrict__ Ah) {
    int warp = (int)((blockIdx.x * (long)blockDim.x + threadIdx.x) >> 5);
    int lane = threadIdx.x & 31;
    if (warp >= NN) return;
    int o0 = off[warp], o1 = off[warp + 1];
    float4 a0 = make_float4(0.f, 0.f, 0.f, 0.f);
    float4 a1 = a0, a2 = a0;
    for (int j = o0; j < o1; j++) {
        int s = csr[j];
        float ns = nsrc[s];
        const uint2* xr = (const uint2*)(g_xh + (size_t)s * DD);   // 75 uint2 per row
        uint2 u = xr[lane];
        float2 p0 = __half22float2(*(fp162*)&u.x);
        float2 p1 = __half22float2(*(fp162*)&u.y);
        a0.x += p0.x * ns; a0.y += p0.y * ns; a0.z += p1.x * ns; a0.w += p1.y * ns;
        u = xr[32 + lane];
        p0 = __half22float2(*(fp162*)&u.x);
        p1 = __half22float2(*(fp162*)&u.y);
        a1.x += p0.x * ns; a1.y += p0.y * ns; a1.z += p1.x * ns; a1.w += p1.y * ns;
        if (lane < 11) {
            u = xr[64 + lane];
            p0 = __half22float2(*(fp162*)&u.x);
            p1 = __half22float2(*(fp162*)&u.y);
            a2.x += p0.x * ns; a2.y += p0.y * ns; a2.z += p1.x * ns; a2.w += p1.y * ns;
        }
    }
    float nd = ndst[warp];
    size_t orow = (size_t)warp * KP1;
    auto store4 = [&](float4 a, int f4i) {
        uint2 hh = make_uint2(
            pack2(__float2half(a.x * nd), __float2half(a.y * nd)),
            pack2(__float2half(a.z * nd), __float2half(a.w * nd)));
        *(uint2*)&Ah[orow + f4i * 4] = hh;
    };
    store4(a0, lane);
    store4(a1, 32 + lane);
    if (lane < 11) store4(a2, 64 + lane);
    if (lane < 20) Ah[orow + 300 + lane] = __float2half(0.f);
}

// zero tail rows [NN, MP) of agg + mrg planes
__global__ void tail_zero_kernel() {
    int i = blockIdx.x * blockDim.x + threadIdx.x;
    const int nAgg = (MP - NN) * KP1;
    const int nMrg = (MP - NN) * KPM;
    fp16 z = __float2half(0.f);
    if (i < nAgg) {
        size_t o = (size_t)NN * KP1 + i;
        g_aggr[o] = z;
        g_aggc[o] = z;
    }
    if (i < nMrg) g_mrg[(size_t)NN * KPM + i] = z;
}

// weight (K x Ncols fp32) -> fp16 plane (KPp x NP), zero padded
__global__ void w_convert_kernel(const float* __restrict__ W, int K, int Ncols, int KPp,
                                 fp16* __restrict__ Wh) {
    int idx = blockIdx.x * blockDim.x + threadIdx.x;
    if (idx >= KPp * NP) return;
    int k = idx / NP;
    int n = idx - k * NP;
    float v = (k < K && n < Ncols) ? W[(size_t)k * Ncols + n] : 0.f;
    Wh[idx] = __float2half(v);
}

// ====== Tensor-core GEMM: fp16 single-pass, SW128, GBK=64, 2-stage ==========
// mode 0: fp32 out (guarded). mode 1: fp16 plane, zero-fill full padded tile.
// mode 2: fp16 out, store ONLY valid elements (for aliased mrg halves).
#define GBM 128
#define GBN 64
#define GBK 64
#define A_PL 16384u
#define B_PL 8192u
#define STG (A_PL + B_PL)           // 24576
#define SMEM_GEMM (2 * STG)         // 49152

__global__ __launch_bounds__(256) void gemm_tc2_kernel(
    const fp16* __restrict__ Ap, int lda,
    const fp16* __restrict__ Bp,
    const float* __restrict__ bias,
    int M, int Ncols, int nK, int mode, int relu,
    float* __restrict__ Cf, int ldc,
    fp16* __restrict__ Ch, int ldcp)
{
    extern __shared__ __align__(128) char smem[];
    const uint32_t sb = (uint32_t)__cvta_generic_to_shared(smem);

    const int t = threadIdx.x;
    const int wid = t >> 5;
    const int lane = t & 31;
    const int warp_m = wid >> 1;
    const int warp_n = wid & 1;
    const int m0 = blockIdx.y * GBM;
    const int n0 = blockIdx.x * GBN;

    float acc[2][4][4];
    #pragma unroll
    for (int mi = 0; mi < 2; mi++)
        #pragma unroll
        for (int ni = 0; ni < 4; ni++)
            #pragma unroll
            for (int j = 0; j < 4; j++) acc[mi][ni][j] = 0.f;

    auto load_stage = [&](int stage, int k0) {
        const uint32_t base = sb + (uint32_t)stage * STG;
        const uint32_t aA = base;
        const uint32_t aB = base + A_PL;
        #pragma unroll
        for (int i = 0; i < 4; i++) {
            int idx = i * 256 + t;
            int r = idx >> 3, c = idx & 7;
            uint32_t d = SWZ((uint32_t)(r * 128 + c * 16));
            cp16(aA + d, Ap + (size_t)(m0 + r) * lda + k0 + c * 8);
        }
        #pragma unroll
        for (int i = 0; i < 2; i++) {
            int idx = i * 256 + t;
            int r = idx >> 3, c = idx & 7;
            uint32_t d = SWZ((uint32_t)(r * 128 + c * 16));
            cp16(aB + d, Bp + (size_t)(k0 + r) * NP + n0 + c * 8);
        }
        asm volatile("cp.async.commit_group;");
    };

    load_stage(0, 0);

    const int lrow = lane & 15;
    const int lhi = lane >> 4;

    for (int kt = 0; kt < nK; kt++) {
        if (kt + 1 < nK) {
            load_stage((kt + 1) & 1, (kt + 1) * GBK);
            asm volatile("cp.async.wait_group 1;");
        } else {
            asm volatile("cp.async.wait_group 0;");
        }
        __syncthreads();

        const uint32_t base = sb + (uint32_t)(kt & 1) * STG;
        const uint32_t aA = base;
        const uint32_t aB = base + A_PL;

        #pragma unroll
        for (int ks = 0; ks < 4; ks++) {
            uint32_t ah[2][4];
            #pragma unroll
            for (int mi = 0; mi < 2; mi++) {
                int row = warp_m * 32 + mi * 16 + lrow;
                uint32_t off = SWZ((uint32_t)(row * 128 + ks * 32 + lhi * 16));
                ldsm_x4(ah[mi][0], ah[mi][1], ah[mi][2], ah[mi][3], aA + off);
            }
            uint32_t bh[4][2];
            #pragma unroll
            for (int nj = 0; nj < 2; nj++) {
                int krow = ks * 16 + lrow;
                uint32_t off = SWZ((uint32_t)(krow * 128 + warp_n * 64 + nj * 32 + lhi * 16));
                uint32_t r0, r1, r2, r3;
                ldsm_x4_t(r0, r1, r2, r3, aB + off);
                bh[nj * 2 + 0][0] = r0; bh[nj * 2 + 0][1] = r1;
                bh[nj * 2 + 1][0] = r2; bh[nj * 2 + 1][1] = r3;
            }
            #pragma unroll
            for (int mi = 0; mi < 2; mi++)
                #pragma unroll
                for (int ni = 0; ni < 4; ni++)
                    mma_fp16(acc[mi][ni], ah[mi], bh[ni]);
        }
        __syncthreads();
    }

    // ---- epilogue ----
    const int g = lane >> 2;
    const int tig = lane & 3;
    #pragma unroll
    for (int mi = 0; mi < 2; mi++) {
        #pragma unroll
        for (int ni = 0; ni < 4; ni++) {
            int col = n0 + warp_n * 32 + ni * 8 + tig * 2;
            float bx = 0.f, by = 0.f;
            if (bias != nullptr && col < Ncols) {
                bx = bias[col];
                if (col + 1 < Ncols) by = bias[col + 1];
            }
            #pragma unroll
            for (int rr = 0; rr < 2; rr++) {
                int row = m0 + warp_m * 32 + mi * 16 + g + rr * 8;
                float vx = acc[mi][ni][rr * 2 + 0] + bx;
                float vy = acc[mi][ni][rr * 2 + 1] + by;
                if (relu) { vx = fmaxf(vx, 0.f); vy = fmaxf(vy, 0.f); }
                bool ok = (row < M) && (col < Ncols);
                if (mode == 0) {
                    if (ok)
                        *(float2*)(Cf + (size_t)row * ldc + col) = make_float2(vx, vy);
                } else if (mode == 1) {
                    if (!ok) { vx = 0.f; vy = 0.f; }
                    *(uint32_t*)&Ch[(size_t)row * ldcp + col] =
                        pack2(__float2half(vx), __float2half(vy));
                } else {            // mode 2: store only valid (aliased target)
                    if (ok)
                        *(uint32_t*)&Ch[(size_t)row * ldcp + col] =
                            pack2(__float2half(vx), __float2half(vy));
                }
            }
        }
    }
}

// ---------------- LayerNorm (fp32, in place) --------------------------------
__global__ void ln_kernel(float* __restrict__ X, int ld,
                          const float* __restrict__ gamma,
                          const float* __restrict__ beta, int M) {
    int warp = (int)((blockIdx.x * (long)blockDim.x + threadIdx.x) >> 5);
    int lane = threadIdx.x & 31;
    if (warp >= M) return;
    float* p = X + (size_t)warp * ld;
    float v[10];
    float sum = 0.f;
    #pragma unroll
    for (int k = 0; k < 10; k++) {
        int c = lane + 32 * k;
        v[k] = (c < DD) ? p[c] : 0.f;
        sum += v[k];
    }
    #pragma unroll
    for (int o = 16; o > 0; o >>= 1) sum += __shfl_xor_sync(0xFFFFFFFFu, sum, o);
    float mu = sum * (1.f / DD);
    float var = 0.f;
    #pragma unroll
    for (int k = 0; k < 10; k++) {
        int c = lane + 32 * k;
        float d = (c < DD) ? (v[k] - mu) : 0.f;
        var += d * d;
    }
    #pragma unroll
    for (int o = 16; o > 0; o >>= 1) var += __shfl_xor_sync(0xFFFFFFFFu, var, o);
    float rsig = rsqrtf(var * (1.f / DD) + 1e-5f);
    #pragma unroll
    for (int k = 0; k < 10; k++) {
        int c = lane + 32 * k;
        if (c < DD) p[c] = (v[k] - mu) * rsig * gamma[c] + beta[c];
    }
}

// in-place LN on the two fp16 halves of each mrg row; zero pad cols [600,640)
__global__ void ln_mrg_kernel(const float* __restrict__ g0, const float* __restrict__ b0,
                              const float* __restrict__ g1, const float* __restrict__ b1) {
    int warp = (int)((blockIdx.x * (long)blockDim.x + threadIdx.x) >> 5);
    int lane = threadIdx.x & 31;
    if (warp >= NN) return;
    size_t orow = (size_t)warp * KPM;
    #pragma unroll
    for (int half = 0; half < 2; half++) {
        fp16* p = g_mrg + orow + half * DD;
        const float* gamma = half ? g1 : g0;
        const float* beta  = half ? b1 : b0;
        float v[10];
        float sum = 0.f;
        #pragma unroll
        for (int k = 0; k < 10; k++) {
            int c = lane + 32 * k;
            v[k] = (c < DD) ? __half2float(p[c]) : 0.f;
            sum += v[k];
        }
        #pragma unroll
        for (int o = 16; o > 0; o >>= 1) sum += __shfl_xor_sync(0xFFFFFFFFu, sum, o);
        float mu = sum * (1.f / DD);
        float var = 0.f;
        #pragma unroll
        for (int k = 0; k < 10; k++) {
            int c = lane + 32 * k;
            float d = (c < DD) ? (v[k] - mu) : 0.f;
            var += d * d;
        }
        #pragma unroll
        for (int o = 16; o > 0; o >>= 1) var += __shfl_xor_sync(0xFFFFFFFFu, var, o);
        float rsig = rsqrtf(var * (1.f / DD) + 1e-5f);
        #pragma unroll
        for (int k = 0; k < 10; k++) {
            int c = lane + 32 * k;
            if (c < DD)
                p[c] = __float2half((v[k] - mu) * rsig * gamma[c] + beta[c]);
        }
    }
    fp16 z = __float2half(0.f);
    g_mrg[orow + 600 + lane] = z;
    if (lane < 8) g_mrg[orow + 632 + lane] = z;
}

// ---------------- launch ----------------------------------------------------
extern "C" void kernel_launch(void* const* d_in, const int* in_sizes, int n_in,
                              void* d_out, int out_size) {
    const float* x    = (const float*)d_in[0];
    const int*   er   = (const int*)d_in[1];
    const int*   ec   = (const int*)d_in[2];
    const float* Wr   = (const float*)d_in[3];
    const float* br   = (const float*)d_in[4];
    const float* Wc   = (const float*)d_in[5];
    const float* bc   = (const float*)d_in[6];
    const float* Wrs  = (const float*)d_in[7];
    const float* brs  = (const float*)d_in[8];
    const float* g_rs = (const float*)d_in[9];
    const float* b_rs = (const float*)d_in[10];
    const float* Wcs  = (const float*)d_in[11];
    const float* bcs  = (const float*)d_in[12];
    const float* g_cs = (const float*)d_in[13];
    const float* b_cs = (const float*)d_in[14];
    const float* Wm   = (const float*)d_in[15];
    const float* bm   = (const float*)d_in[16];
    const float* g_m  = (const float*)d_in[17];
    const float* b_m  = (const float*)d_in[18];
    float* out = (float*)d_out;

    float* deg;
    cudaGetSymbolAddress((void**)&deg, g_deg);
    int *off_r, *off_c, *cur_r, *cur_c, *csr_r, *csr_c;
    cudaGetSymbolAddress((void**)&off_r, g_off_r);
    cudaGetSymbolAddress((void**)&off_c, g_off_c);
    cudaGetSymbolAddress((void**)&cur_r, g_cur_r);
    cudaGetSymbolAddress((void**)&cur_c, g_cur_c);
    cudaGetSymbolAddress((void**)&csr_r, g_csr_r);
    cudaGetSymbolAddress((void**)&csr_c, g_csr_c);

    fp16 *aggr, *aggc, *rowg, *colg, *mrg;
    fp16 *pWr, *pWc, *pWrs, *pWcs, *pWm;
    cudaGetSymbolAddress((void**)&aggr, g_aggr);
    cudaGetSymbolAddress((void**)&aggc, g_aggc);
    cudaGetSymbolAddress((void**)&rowg, g_rowg);
    cudaGetSymbolAddress((void**)&colg, g_colg);
    cudaGetSymbolAddress((void**)&mrg,  g_mrg);
    cudaGetSymbolAddress((void**)&pWr,  g_Wr);
    cudaGetSymbolAddress((void**)&pWc,  g_Wc);
    cudaGetSymbolAddress((void**)&pWrs, g_Wrs);
    cudaGetSymbolAddress((void**)&pWcs, g_Wcs);
    cudaGetSymbolAddress((void**)&pWm,  g_Wm);

    cudaFuncSetAttribute(gemm_tc2_kernel,
                         cudaFuncAttributeMaxDynamicSharedMemorySize, SMEM_GEMM);

    // graph preprocessing + x conversion
    zero_ideg_kernel<<<(4 * NN + 255) / 256, 256>>>();
    degree_kernel<<<(NE + 255) / 256, 256>>>(er, ec);
    x_convert_kernel<<<(int)(((long)NN * DD / 2 + 255) / 256), 256>>>((const float2*)x);
    norm_kernel<<<(4 * NN + 255) / 256, 256>>>();
    dim3 sgrid(NSB, 2);
    scan1_kernel<<<sgrid, SB>>>();
    scan2_kernel<<<1, 256>>>(off_r, off_c);
    scan3_kernel<<<sgrid, SB>>>(off_r, cur_r, off_c, cur_c);
    fill_kernel<<<(NE + 255) / 256, 256>>>(er, cur_r, csr_r);
    fill_kernel<<<(NE + 255) / 256, 256>>>(ec, cur_c, csr_c);
    int ggrid = (NN * 32 + 255) / 256;
    gather_kernel<<<ggrid, 256>>>(csr_r, off_r, deg + 0 * NN, deg + 1 * NN, aggr);
    gather_kernel<<<ggrid, 256>>>(csr_c, off_c, deg + 2 * NN, deg + 3 * NN, aggc);
    tail_zero_kernel<<<((MP - NN) * KPM + 255) / 256, 256>>>();

    // weight converts
    int wgrid = (KP1 * NP + 255) / 256;
    w_convert_kernel<<<wgrid, 256>>>(Wr,  DD, DD, KP1, pWr);
    w_convert_kernel<<<wgrid, 256>>>(Wc,  DD, DD, KP1, pWc);
    w_convert_kernel<<<wgrid, 256>>>(Wrs, DD, DD, KP1, pWrs);
    w_convert_kernel<<<wgrid, 256>>>(Wcs, DD, DD, KP1, pWcs);
    w_convert_kernel<<<(KPM * NP + 255) / 256, 256>>>(Wm, 2 * DD, DD, KPM, pWm);

    dim3 gg(NP / GBN, MP / GBM);   // (5, 782)
    const int nK1 = KP1 / GBK;     // 5
    const int nKm = KPM / GBK;     // 10

    // GraphConv GEMMs -> relu -> fp16 planes (zero-filled padding)
    gemm_tc2_kernel<<<gg, 256, SMEM_GEMM>>>(aggr, KP1, pWr, br,
        NN, DD, nK1, 1, 1, nullptr, 0, rowg, KP1);
    gemm_tc2_kernel<<<gg, 256, SMEM_GEMM>>>(aggc, KP1, pWc, bc,
        NN, DD, nK1, 1, 1, nullptr, 0, colg, KP1);

    // support GEMMs -> fp16 mrg halves directly (mode 2: valid-only stores)
    gemm_tc2_kernel<<<gg, 256, SMEM_GEMM>>>(rowg, KP1, pWrs, brs,
        NN, DD, nK1, 2, 0, nullptr, 0, mrg, KPM);
    gemm_tc2_kernel<<<gg, 256, SMEM_GEMM>>>(colg, KP1, pWcs, bcs,
        NN, DD, nK1, 2, 0, nullptr, 0, mrg + DD, KPM);

    // in-place fp16 LN on both halves (+ zero pad cols)
    int lngrid = (NN + 7) / 8;
    ln_mrg_kernel<<<lngrid, 256>>>(g_rs, b_rs, g_cs, b_cs);

    // merge GEMM (K=640) -> fp32 out, then final LN
    gemm_tc2_kernel<<<gg, 256, SMEM_GEMM>>>(mrg, KPM, pWm, bm,
        NN, DD, nKm, 0, 0, out, DD, nullptr, 0);
    ln_kernel<<<lngrid, 256>>>(out, DD, g_m, b_m, NN);
}